// round 13
// baseline (speedup 1.0000x reference)
#include <cuda_runtime.h>
#include <cuda_bf16.h>
#include <cstdint>
#include <cstddef>

// ===========================================================================
// Problem constants
// ===========================================================================
constexpr int kB   = 2;
constexpr int kS   = 2048;
constexpr int kD   = 1024;
constexpr int kHID = 1024;
constexpr int kH   = 16;
constexpr int kHD  = 64;
constexpr int kM   = kB * kS;      // 4096
constexpr float kScale = 0.03125f; // 1/sqrt(1024), exact power of two

constexpr int kRW   = kD / 2;      // 512 words per row (K=1024 packed)
constexpr int kQKVW = 3 * kRW;     // 1536 words per qkv row

// ===========================================================================
// Scratch (device globals; allocation-free rule)
// ===========================================================================
__device__ uint32_t g_xs_hi [(size_t)kM * kRW];
__device__ uint32_t g_xs_lo [(size_t)kM * kRW];
__device__ uint32_t g_wall_hi[(size_t)3 * kHID * kRW];
__device__ uint32_t g_wall_lo[(size_t)3 * kHID * kRW];
__device__ uint32_t g_wo_hi [(size_t)kD * kRW];
__device__ uint32_t g_wo_lo [(size_t)kD * kRW];
__device__ float    g_bias_all[3 * kHID];
__device__ uint32_t g_qkv_hi[(size_t)kM * kQKVW];
__device__ uint32_t g_qkv_lo[(size_t)kM * kQKVW];
__device__ uint32_t g_ctx_hi[(size_t)kM * kRW];
__device__ uint32_t g_ctx_lo[(size_t)kM * kRW];

// ===========================================================================
// helpers
// ===========================================================================
__device__ __forceinline__ void mma_bf16(float* d, const uint32_t* a, const uint32_t* b) {
    asm volatile(
        "mma.sync.aligned.m16n8k16.row.col.f32.bf16.bf16.f32 "
        "{%0,%1,%2,%3}, {%4,%5,%6,%7}, {%8,%9}, {%0,%1,%2,%3};"
        : "+f"(d[0]), "+f"(d[1]), "+f"(d[2]), "+f"(d[3])
        : "r"(a[0]), "r"(a[1]), "r"(a[2]), "r"(a[3]),
          "r"(b[0]), "r"(b[1]));
}

__device__ __forceinline__ void ldsm_x4(uint32_t& r0, uint32_t& r1,
                                        uint32_t& r2, uint32_t& r3, uint32_t addr) {
    asm volatile(
        "ldmatrix.sync.aligned.m8n8.x4.shared.b16 {%0,%1,%2,%3}, [%4];"
        : "=r"(r0), "=r"(r1), "=r"(r2), "=r"(r3) : "r"(addr));
}

__device__ __forceinline__ void ldsm_x4_t(uint32_t& r0, uint32_t& r1,
                                          uint32_t& r2, uint32_t& r3, uint32_t addr) {
    asm volatile(
        "ldmatrix.sync.aligned.m8n8.x4.trans.shared.b16 {%0,%1,%2,%3}, [%4];"
        : "=r"(r0), "=r"(r1), "=r"(r2), "=r"(r3) : "r"(addr));
}

__device__ __forceinline__ uint32_t smem_u32(const void* p) {
    uint32_t a;
    asm("{ .reg .u64 t; cvta.to.shared.u64 t, %1; cvt.u32.u64 %0, t; }"
        : "=r"(a) : "l"(p));
    return a;
}

__device__ __forceinline__ void cp_async16(uint32_t smem_addr, const void* gmem) {
    asm volatile("cp.async.cg.shared.global [%0], [%1], 16;"
                 :: "r"(smem_addr), "l"(gmem));
}
__device__ __forceinline__ void cp_commit() {
    asm volatile("cp.async.commit_group;");
}
__device__ __forceinline__ void cp_wait0() {
    asm volatile("cp.async.wait_group 0;");
}

// pack two floats into bf16x2 word (x0 -> low) + residual word
__device__ __forceinline__ void bf16x2_split(float x0, float x1,
                                             uint32_t& hi, uint32_t& lo) {
    __nv_bfloat16 h0 = __float2bfloat16_rn(x0);
    __nv_bfloat16 h1 = __float2bfloat16_rn(x1);
    float r0 = x0 - __bfloat162float(h0);
    float r1 = x1 - __bfloat162float(h1);
    __nv_bfloat16 l0 = __float2bfloat16_rn(r0);
    __nv_bfloat16 l1 = __float2bfloat16_rn(r1);
    hi = ((uint32_t)__bfloat16_as_ushort(h1) << 16) | __bfloat16_as_ushort(h0);
    lo = ((uint32_t)__bfloat16_as_ushort(l1) << 16) | __bfloat16_as_ushort(l0);
}

// ===========================================================================
// split kernels
// ===========================================================================
__global__ void split_kernel(const float* __restrict__ src,
                             uint32_t* __restrict__ hi,
                             uint32_t* __restrict__ lo, int n4)
{
    int i = blockIdx.x * blockDim.x + threadIdx.x;
    if (i >= n4) return;
    float4 v = ((const float4*)src)[i];
    uint32_t h0, l0, h1, l1;
    bf16x2_split(v.x, v.y, h0, l0);
    bf16x2_split(v.z, v.w, h1, l1);
    ((uint2*)hi)[i] = make_uint2(h0, h1);
    ((uint2*)lo)[i] = make_uint2(l0, l1);
}

__global__ void split_w4_kernel(const float* __restrict__ Wq,
                                const float* __restrict__ Wk,
                                const float* __restrict__ Wv,
                                const float* __restrict__ Wo,
                                uint32_t* __restrict__ wall_hi,
                                uint32_t* __restrict__ wall_lo,
                                uint32_t* __restrict__ wo_hi,
                                uint32_t* __restrict__ wo_lo,
                                int n4region)
{
    int gi = blockIdx.x * blockDim.x + threadIdx.x;
    int region = gi / n4region;
    int i = gi - region * n4region;
    const float* src = (region == 0) ? Wq : (region == 1) ? Wk
                     : (region == 2) ? Wv : Wo;
    uint32_t* hi = (region < 3) ? wall_hi + (size_t)region * 2 * n4region : wo_hi;
    uint32_t* lo = (region < 3) ? wall_lo + (size_t)region * 2 * n4region : wo_lo;
    float4 v = ((const float4*)src)[i];
    uint32_t h0, l0, h1, l1;
    bf16x2_split(v.x, v.y, h0, l0);
    bf16x2_split(v.z, v.w, h1, l1);
    ((uint2*)hi)[i] = make_uint2(h0, h1);
    ((uint2*)lo)[i] = make_uint2(l0, l1);
}

__global__ void bias3_kernel(const float* __restrict__ bq,
                             const float* __restrict__ bk,
                             const float* __restrict__ bv,
                             float* __restrict__ dst)
{
    int i = blockIdx.x * blockDim.x + threadIdx.x;
    if (i < kHID)              dst[i] = bq[i];
    else if (i < 2 * kHID)     dst[i] = bk[i - kHID];
    else if (i < 3 * kHID)     dst[i] = bv[i - 2 * kHID];
}

// ===========================================================================
// bf16x3 GEMM: cp.async 2-stage, 2 CTAs/SM, ldmatrix,
// term-major mma ordering (same-accumulator distance 4).
// ===========================================================================
constexpr int GW    = 16;
constexpr int GSTR  = 20;
constexpr int GT    = 128 * GSTR;
constexpr int GSTAGE = 4 * GT;
constexpr int GEMM_SMEM = 2 * GSTAGE * 4;   // 81920 B

__global__ __launch_bounds__(256, 2)
void gemm_bf16x3(const uint32_t* __restrict__ Ah, const uint32_t* __restrict__ Al,
                 const uint32_t* __restrict__ Bh, const uint32_t* __restrict__ Bl,
                 const float* __restrict__ bias,
                 float* __restrict__ Cf,
                 uint32_t* __restrict__ Ch, uint32_t* __restrict__ Cl,
                 int M, int N, int K, int scaleCols, float scaleVal)
{
    extern __shared__ uint32_t smw[];
    const uint32_t sb = smem_u32(smw);

    const int tid  = threadIdx.x;
    const int wid  = tid >> 5;
    const int lane = tid & 31;
    const int g    = lane >> 2;
    const int t    = lane & 3;

    const int wm = (wid & 3) * 32;
    const int wn = (wid >> 2) * 64;

    const int lm8 = lane & 7;
    const int lq  = lane >> 3;
    const int a_row = lm8 + (lq & 1) * 8;
    const int a_wof = (lq >> 1) * 4;
    const int b_row = lm8 + (lq >> 1) * 8;
    const int b_wof = (lq & 1) * 4;

    const int brow = blockIdx.y * 128;
    const int bcol = blockIdx.x * 128;
    const int kw   = K >> 1;
    const int nchunks = K / 32;

    const int lr0 = tid >> 2;
    const int lw4 = (tid & 3) * 4;

    float acc[2][8][4];
    #pragma unroll
    for (int mi = 0; mi < 2; mi++)
        #pragma unroll
        for (int nf = 0; nf < 8; nf++)
            #pragma unroll
            for (int j = 0; j < 4; j++) acc[mi][nf][j] = 0.f;

    auto cpa_chunk = [&](int c, int buf) {
        const uint32_t s = sb + (uint32_t)((buf * GSTAGE) << 2);
        const uint32_t* a_h = Ah + (size_t)brow * kw + c * GW + lw4;
        const uint32_t* a_l = Al + (size_t)brow * kw + c * GW + lw4;
        const uint32_t* b_h = Bh + (size_t)bcol * kw + c * GW + lw4;
        const uint32_t* b_l = Bl + (size_t)bcol * kw + c * GW + lw4;
        #pragma unroll
        for (int j = 0; j < 2; j++) {
            const int r = lr0 + 64 * j;
            const uint32_t d = (uint32_t)((r * GSTR + lw4) << 2);
            cp_async16(s + ((0 * GT) << 2) + d, a_h + (size_t)r * kw);
            cp_async16(s + ((1 * GT) << 2) + d, a_l + (size_t)r * kw);
            cp_async16(s + ((2 * GT) << 2) + d, b_h + (size_t)r * kw);
            cp_async16(s + ((3 * GT) << 2) + d, b_l + (size_t)r * kw);
        }
        cp_commit();
    };

    cpa_chunk(0, 0);

    for (int c = 0; c < nchunks; c++) {
        cp_wait0();
        __syncthreads();
        if (c + 1 < nchunks) cpa_chunk(c + 1, (c + 1) & 1);

        const uint32_t base = sb + (uint32_t)(((c & 1) * GSTAGE) << 2);

        #pragma unroll
        for (int kk = 0; kk < 2; kk++) {
            const int k0 = kk * 8;
            uint32_t aH[2][4], aL[2][4];
            #pragma unroll
            for (int mi = 0; mi < 2; mi++) {
                uint32_t arow = (uint32_t)((wm + mi * 16 + a_row) * GSTR + k0 + a_wof);
                ldsm_x4(aH[mi][0], aH[mi][1], aH[mi][2], aH[mi][3],
                        base + ((0 * GT + arow) << 2));
                ldsm_x4(aL[mi][0], aL[mi][1], aL[mi][2], aL[mi][3],
                        base + ((1 * GT + arow) << 2));
            }
            #pragma unroll
            for (int np = 0; np < 4; np++) {
                uint32_t nrow = (uint32_t)((wn + np * 16 + b_row) * GSTR + k0 + b_wof);
                uint32_t bh[4], bl[4];
                ldsm_x4(bh[0], bh[1], bh[2], bh[3], base + ((2 * GT + nrow) << 2));
                ldsm_x4(bl[0], bl[1], bl[2], bl[3], base + ((3 * GT + nrow) << 2));
                // term-major: same accumulator revisited at distance 4
                #pragma unroll
                for (int mi = 0; mi < 2; mi++)
                    #pragma unroll
                    for (int half = 0; half < 2; half++)
                        mma_bf16(acc[mi][np * 2 + half], aH[mi], bh + 2 * half);
                #pragma unroll
                for (int mi = 0; mi < 2; mi++)
                    #pragma unroll
                    for (int half = 0; half < 2; half++)
                        mma_bf16(acc[mi][np * 2 + half], aH[mi], bl + 2 * half);
                #pragma unroll
                for (int mi = 0; mi < 2; mi++)
                    #pragma unroll
                    for (int half = 0; half < 2; half++)
                        mma_bf16(acc[mi][np * 2 + half], aL[mi], bh + 2 * half);
            }
        }
    }

    const int nw = N >> 1;
    #pragma unroll
    for (int mi = 0; mi < 2; mi++) {
        const int r0 = brow + wm + mi * 16 + g;
        #pragma unroll
        for (int nf = 0; nf < 8; nf++) {
            const int c0 = bcol + wn + nf * 8 + 2 * t;
            float bx = bias[c0], by = bias[c0 + 1];
            float v0 = acc[mi][nf][0] + bx, v1 = acc[mi][nf][1] + by;
            float v2 = acc[mi][nf][2] + bx, v3 = acc[mi][nf][3] + by;
            if (Cf) {
                *(float2*)(Cf + (size_t)r0 * N + c0)       = make_float2(v0, v1);
                *(float2*)(Cf + (size_t)(r0 + 8) * N + c0) = make_float2(v2, v3);
            } else {
                float sc = (c0 < scaleCols) ? scaleVal : 1.0f;
                v0 *= sc; v1 *= sc; v2 *= sc; v3 *= sc;
                uint32_t h, l;
                bf16x2_split(v0, v1, h, l);
                Ch[(size_t)r0 * nw + (c0 >> 1)] = h;
                Cl[(size_t)r0 * nw + (c0 >> 1)] = l;
                bf16x2_split(v2, v3, h, l);
                Ch[(size_t)(r0 + 8) * nw + (c0 >> 1)] = h;
                Cl[(size_t)(r0 + 8) * nw + (c0 >> 1)] = l;
            }
        }
    }
}

// ===========================================================================
// bf16x3 flash attention, 2 CTAs/SM, exp/PV interleave,
// np-paired fragment loads + term-major mma (same-acc distance 4).
// ===========================================================================
constexpr int QSTR = 36;                     // padded word stride
constexpr int AT_Q  = 128 * QSTR;            // per half (hi or lo)
constexpr int AT_KV = 64 * QSTR;
constexpr int AT_STAGE = 4 * AT_KV;          // KH KL VH VL
constexpr int ATTN_SMEM = (2 * AT_Q + 2 * AT_STAGE) * 4;  // 110,592 B

__global__ __launch_bounds__(256, 2)
void attn_bf16(const uint32_t* __restrict__ Qh, const uint32_t* __restrict__ Ql,
               uint32_t* __restrict__ Oh, uint32_t* __restrict__ Ol)
{
    extern __shared__ uint32_t smw[];
    const uint32_t sb = smem_u32(smw);
    const uint32_t qhb = sb;                               // QH
    const uint32_t qlb = sb + (uint32_t)(AT_Q << 2);       // QL
    const uint32_t stg = qlb + (uint32_t)(AT_Q << 2);      // stages
    const uint32_t kvb = (uint32_t)(AT_KV << 2);

    const int tid  = threadIdx.x;
    const int w    = tid >> 5;
    const int lane = tid & 31;
    const int g    = lane >> 2;
    const int t    = lane & 3;

    const int lm8 = lane & 7;
    const int lq  = lane >> 3;
    const int a_row = lm8 + (lq & 1) * 8;
    const int a_wof = (lq >> 1) * 4;
    const int b_row = lm8 + (lq >> 1) * 8;
    const int b_wof = (lq & 1) * 4;
    const int v_row = lm8 + (lq & 1) * 8;
    const int v_wof = (lq >> 1) * 4;

    const int bh = blockIdx.y;
    const int b  = bh >> 4;
    const int h  = bh & 15;
    const int q0 = blockIdx.x * 128;

    const size_t rowbase = (size_t)(b * kS) * kQKVW;
    const int qoff = h * 32;
    const int koff = 512 + h * 32;
    const int voff = 1024 + h * 32;

    // ---- stage Q (hi + lo) via cp.async ----
    {
        #pragma unroll
        for (int i = 0; i < 8; i++) {
            int idx = tid + 256 * i;            // 0..2047
            int arr = idx >> 10;                // 0: hi, 1: lo
            int rem = idx & 1023;
            int r   = rem >> 3;
            int ch  = (rem & 7) * 4;
            const uint32_t* src = (arr ? Ql : Qh) + rowbase
                                + (size_t)(q0 + r) * kQKVW + qoff + ch;
            uint32_t dst = (arr ? qlb : qhb) + (uint32_t)((r * QSTR + ch) << 2);
            cp_async16(dst, src);
        }
        cp_commit();
    }

    float o[8][4];
    #pragma unroll
    for (int nf = 0; nf < 8; nf++)
        #pragma unroll
        for (int e = 0; e < 4; e++) o[nf][e] = 0.f;
    float lsum0 = 0.f, lsum1 = 0.f;

    auto cpa_tile = [&](int kt, int buf) {
        const uint32_t s = stg + (uint32_t)((buf * AT_STAGE) << 2);
        #pragma unroll
        for (int i = 0; i < 8; i++) {
            int idx = tid + 256 * i;            // 0..2047
            int arr = idx >> 9;                 // 0:KH 1:KL 2:VH 3:VL
            int rem = idx & 511;
            int key = rem >> 3;
            int ch  = (rem & 7) * 4;
            int off = (arr < 2) ? koff : voff;
            const uint32_t* base = ((arr & 1) ? Ql : Qh);
            const uint32_t* src = base + rowbase
                                + (size_t)(kt + key) * kQKVW + off + ch;
            uint32_t dst = s + (uint32_t)((arr * AT_KV + key * QSTR + ch) << 2);
            cp_async16(dst, src);
        }
        cp_commit();
    };

    cpa_tile(0, 0);

    for (int tI = 0; tI < kS / 64; tI++) {
        cp_wait0();
        __syncthreads();
        if (tI + 1 < kS / 64) cpa_tile((tI + 1) * 64, (tI + 1) & 1);

        const uint32_t stb = stg + (uint32_t)(((tI & 1) * AT_STAGE) << 2);

        // ---- S = qH kH + qL kH + qH kL  (np-paired, term-major) ----
        float s[8][4];
        #pragma unroll
        for (int nf = 0; nf < 8; nf++)
            s[nf][0] = s[nf][1] = s[nf][2] = s[nf][3] = 0.f;

        #pragma unroll
        for (int ks = 0; ks < 4; ks++) {
            const int k0 = ks * 8;
            uint32_t qH[4], qL[4];
            uint32_t qrow = (uint32_t)(((w * 16 + a_row) * QSTR + k0 + a_wof) << 2);
            ldsm_x4(qH[0], qH[1], qH[2], qH[3], qhb + qrow);
            ldsm_x4(qL[0], qL[1], qL[2], qL[3], qlb + qrow);
            #pragma unroll
            for (int npp = 0; npp < 2; npp++) {
                uint32_t kh[2][4], kl[2][4];
                #pragma unroll
                for (int j = 0; j < 2; j++) {
                    const int np = npp * 2 + j;
                    uint32_t roff = (uint32_t)(((np * 16 + b_row) * QSTR + k0 + b_wof) << 2);
                    ldsm_x4(kh[j][0], kh[j][1], kh[j][2], kh[j][3], stb + roff);
                    ldsm_x4(kl[j][0], kl[j][1], kl[j][2], kl[j][3], stb + kvb + roff);
                }
                // term-major: same s[nf] revisited at distance 4
                #pragma unroll
                for (int j = 0; j < 2; j++)
                    #pragma unroll
                    for (int half = 0; half < 2; half++)
                        mma_bf16(s[npp * 4 + j * 2 + half], qH, kh[j] + 2 * half);
                #pragma unroll
                for (int j = 0; j < 2; j++)
                    #pragma unroll
                    for (int half = 0; half < 2; half++)
                        mma_bf16(s[npp * 4 + j * 2 + half], qL, kh[j] + 2 * half);
                #pragma unroll
                for (int j = 0; j < 2; j++)
                    #pragma unroll
                    for (int half = 0; half < 2; half++)
                        mma_bf16(s[npp * 4 + j * 2 + half], qH, kl[j] + 2 * half);
            }
        }

        // ---- per-kc: exp + pack + PV mma (np-paired, term-major) ----
        #pragma unroll
        for (int kc = 0; kc < 4; kc++) {
            float p00 = __expf(s[2*kc][0]);
            float p01 = __expf(s[2*kc][1]);
            float p02 = __expf(s[2*kc][2]);
            float p03 = __expf(s[2*kc][3]);
            float p10 = __expf(s[2*kc+1][0]);
            float p11 = __expf(s[2*kc+1][1]);
            float p12 = __expf(s[2*kc+1][2]);
            float p13 = __expf(s[2*kc+1][3]);
            lsum0 += p00 + p01 + p10 + p11;
            lsum1 += p02 + p03 + p12 + p13;

            uint32_t pah[4], pal[4];
            bf16x2_split(p00, p01, pah[0], pal[0]);
            bf16x2_split(p02, p03, pah[1], pal[1]);
            bf16x2_split(p10, p11, pah[2], pal[2]);
            bf16x2_split(p12, p13, pah[3], pal[3]);

            #pragma unroll
            for (int npp = 0; npp < 2; npp++) {
                uint32_t vh[2][4], vl[2][4];
                #pragma unroll
                for (int j = 0; j < 2; j++) {
                    const int np = npp * 2 + j;
                    uint32_t roff = (uint32_t)(
                        ((kc * 16 + v_row) * QSTR + np * 8 + v_wof) << 2);
                    ldsm_x4_t(vh[j][0], vh[j][1], vh[j][2], vh[j][3],
                              stb + 2 * kvb + roff);
                    ldsm_x4_t(vl[j][0], vl[j][1], vl[j][2], vl[j][3],
                              stb + 3 * kvb + roff);
                }
                // term-major: same o[nf] revisited at distance 4
                #pragma unroll
                for (int j = 0; j < 2; j++)
                    #pragma unroll
                    for (int half = 0; half < 2; half++)
                        mma_bf16(o[npp * 4 + j * 2 + half], pah, vh[j] + 2 * half);
                #pragma unroll
                for (int j = 0; j < 2; j++)
                    #pragma unroll
                    for (int half = 0; half < 2; half++)
                        mma_bf16(o[npp * 4 + j * 2 + half], pal, vh[j] + 2 * half);
                #pragma unroll
                for (int j = 0; j < 2; j++)
                    #pragma unroll
                    for (int half = 0; half < 2; half++)
                        mma_bf16(o[npp * 4 + j * 2 + half], pah, vl[j] + 2 * half);
            }
        }
    }

    // ---- reduce, normalize, split-pack, store ctx ----
    lsum0 += __shfl_xor_sync(0xFFFFFFFFu, lsum0, 1);
    lsum0 += __shfl_xor_sync(0xFFFFFFFFu, lsum0, 2);
    lsum1 += __shfl_xor_sync(0xFFFFFFFFu, lsum1, 1);
    lsum1 += __shfl_xor_sync(0xFFFFFFFFu, lsum1, 2);
    const float inv0 = 1.f / lsum0;
    const float inv1 = 1.f / lsum1;

    const size_t row0 = (size_t)(b * kS + q0 + w * 16 + g);
    #pragma unroll
    for (int nf = 0; nf < 8; nf++) {
        const int cw = h * 32 + nf * 4 + t;
        uint32_t hw, lw;
        bf16x2_split(o[nf][0] * inv0, o[nf][1] * inv0, hw, lw);
        Oh[row0 * kRW + cw] = hw;
        Ol[row0 * kRW + cw] = lw;
        bf16x2_split(o[nf][2] * inv1, o[nf][3] * inv1, hw, lw);
        Oh[(row0 + 8) * kRW + cw] = hw;
        Ol[(row0 + 8) * kRW + cw] = lw;
    }
}

// ===========================================================================
// launch
// ===========================================================================
extern "C" void kernel_launch(void* const* d_in, const int* in_sizes, int n_in,
                              void* d_out, int out_size)
{
    const float* x  = (const float*)d_in[0];
    const float* Wq = (const float*)d_in[1];
    const float* bq = (const float*)d_in[2];
    const float* Wk = (const float*)d_in[3];
    const float* bk = (const float*)d_in[4];
    const float* Wv = (const float*)d_in[5];
    const float* bv = (const float*)d_in[6];
    const float* Wo = (const float*)d_in[7];
    const float* bo = (const float*)d_in[8];
    float* out = (float*)d_out;

    uint32_t *xs_hi, *xs_lo, *wall_hi, *wall_lo, *wo_hi, *wo_lo;
    uint32_t *qkv_hi, *qkv_lo, *ctx_hi, *ctx_lo;
    float* bias_all;
    cudaGetSymbolAddress((void**)&xs_hi,   g_xs_hi);
    cudaGetSymbolAddress((void**)&xs_lo,   g_xs_lo);
    cudaGetSymbolAddress((void**)&wall_hi, g_wall_hi);
    cudaGetSymbolAddress((void**)&wall_lo, g_wall_lo);
    cudaGetSymbolAddress((void**)&wo_hi,   g_wo_hi);
    cudaGetSymbolAddress((void**)&wo_lo,   g_wo_lo);
    cudaGetSymbolAddress((void**)&bias_all,g_bias_all);
    cudaGetSymbolAddress((void**)&qkv_hi,  g_qkv_hi);
    cudaGetSymbolAddress((void**)&qkv_lo,  g_qkv_lo);
    cudaGetSymbolAddress((void**)&ctx_hi,  g_ctx_hi);
    cudaGetSymbolAddress((void**)&ctx_lo,  g_ctx_lo);

    cudaFuncSetAttribute(gemm_bf16x3,
                         cudaFuncAttributeMaxDynamicSharedMemorySize, GEMM_SMEM);
    cudaFuncSetAttribute(attn_bf16,
                         cudaFuncAttributeMaxDynamicSharedMemorySize, ATTN_SMEM);

    const int wq4 = kHID * kD / 4;   // 262144
    split_kernel<<<kM * kD / 4 / 256, 256>>>(x, xs_hi, xs_lo, kM * kD / 4);
    split_w4_kernel<<<4 * wq4 / 256, 256>>>(Wq, Wk, Wv, Wo,
                                            wall_hi, wall_lo, wo_hi, wo_lo, wq4);
    bias3_kernel<<<12, 256>>>(bq, bk, bv, bias_all);

    // fused QKV projection (3-term): M=4096, N=3072, Q scaled by 1/32
    dim3 gqkv(3 * kHID / 128, kM / 128);   // (24, 32)
    gemm_bf16x3<<<gqkv, 256, GEMM_SMEM>>>(
        xs_hi, xs_lo, wall_hi, wall_lo, bias_all,
        nullptr, qkv_hi, qkv_lo, kM, 3 * kHID, kD, kHID, kScale);

    dim3 ga(kS / 128, kB * kH);            // (16, 32)
    attn_bf16<<<ga, 256, ATTN_SMEM>>>(qkv_hi, qkv_lo, ctx_hi, ctx_lo);

    // output projection (3-term)
    dim3 go(kD / 128, kM / 128);           // (8, 32)
    gemm_bf16x3<<<go, 256, GEMM_SMEM>>>(
        ctx_hi, ctx_lo, wo_hi, wo_lo, bo,
        out, nullptr, nullptr, kM, kD, kHID, 0, 1.0f);
}

// round 14
// speedup vs baseline: 1.1406x; 1.1406x over previous
#include <cuda_runtime.h>
#include <cuda_bf16.h>
#include <cuda_fp16.h>
#include <cstdint>
#include <cstddef>

// ===========================================================================
// Problem constants
// ===========================================================================
constexpr int kB   = 2;
constexpr int kS   = 2048;
constexpr int kD   = 1024;
constexpr int kHID = 1024;
constexpr int kH   = 16;
constexpr int kHD  = 64;
constexpr int kM   = kB * kS;      // 4096
constexpr float kScale = 0.03125f; // 1/sqrt(1024), exact power of two

constexpr int kRW   = kD / 2;      // 512 words per row (K=1024 packed)
constexpr int kQKVW = 3 * kRW;     // 1536 words per qkv row

// ===========================================================================
// Scratch (device globals; allocation-free rule)
// ===========================================================================
__device__ uint32_t g_xs_hi [(size_t)kM * kRW];
__device__ uint32_t g_xs_lo [(size_t)kM * kRW];
__device__ uint32_t g_wall_hi[(size_t)3 * kHID * kRW];
__device__ uint32_t g_wall_lo[(size_t)3 * kHID * kRW];
__device__ uint32_t g_wo_hi [(size_t)kD * kRW];
__device__ uint32_t g_wo_lo [(size_t)kD * kRW];
__device__ float    g_bias_all[3 * kHID];
__device__ uint32_t g_qkv_hi[(size_t)kM * kQKVW];
__device__ uint32_t g_qkv_lo[(size_t)kM * kQKVW];
__device__ uint32_t g_ctx_hi[(size_t)kM * kRW];
__device__ uint32_t g_ctx_lo[(size_t)kM * kRW];

// ===========================================================================
// helpers
// ===========================================================================
__device__ __forceinline__ void mma_bf16(float* d, const uint32_t* a, const uint32_t* b) {
    asm volatile(
        "mma.sync.aligned.m16n8k16.row.col.f32.bf16.bf16.f32 "
        "{%0,%1,%2,%3}, {%4,%5,%6,%7}, {%8,%9}, {%0,%1,%2,%3};"
        : "+f"(d[0]), "+f"(d[1]), "+f"(d[2]), "+f"(d[3])
        : "r"(a[0]), "r"(a[1]), "r"(a[2]), "r"(a[3]),
          "r"(b[0]), "r"(b[1]));
}

__device__ __forceinline__ void mma_f16(float* d, const uint32_t* a, const uint32_t* b) {
    asm volatile(
        "mma.sync.aligned.m16n8k16.row.col.f32.f16.f16.f32 "
        "{%0,%1,%2,%3}, {%4,%5,%6,%7}, {%8,%9}, {%0,%1,%2,%3};"
        : "+f"(d[0]), "+f"(d[1]), "+f"(d[2]), "+f"(d[3])
        : "r"(a[0]), "r"(a[1]), "r"(a[2]), "r"(a[3]),
          "r"(b[0]), "r"(b[1]));
}

__device__ __forceinline__ void ldsm_x4(uint32_t& r0, uint32_t& r1,
                                        uint32_t& r2, uint32_t& r3, uint32_t addr) {
    asm volatile(
        "ldmatrix.sync.aligned.m8n8.x4.shared.b16 {%0,%1,%2,%3}, [%4];"
        : "=r"(r0), "=r"(r1), "=r"(r2), "=r"(r3) : "r"(addr));
}

__device__ __forceinline__ void ldsm_x4_t(uint32_t& r0, uint32_t& r1,
                                          uint32_t& r2, uint32_t& r3, uint32_t addr) {
    asm volatile(
        "ldmatrix.sync.aligned.m8n8.x4.trans.shared.b16 {%0,%1,%2,%3}, [%4];"
        : "=r"(r0), "=r"(r1), "=r"(r2), "=r"(r3) : "r"(addr));
}

__device__ __forceinline__ uint32_t smem_u32(const void* p) {
    uint32_t a;
    asm("{ .reg .u64 t; cvta.to.shared.u64 t, %1; cvt.u32.u64 %0, t; }"
        : "=r"(a) : "l"(p));
    return a;
}

__device__ __forceinline__ void cp_async16(uint32_t smem_addr, const void* gmem) {
    asm volatile("cp.async.cg.shared.global [%0], [%1], 16;"
                 :: "r"(smem_addr), "l"(gmem));
}
__device__ __forceinline__ void cp_commit() {
    asm volatile("cp.async.commit_group;");
}
__device__ __forceinline__ void cp_wait0() {
    asm volatile("cp.async.wait_group 0;");
}

// pack two floats into bf16x2 word (x0 -> low) + residual word
__device__ __forceinline__ void bf16x2_split(float x0, float x1,
                                             uint32_t& hi, uint32_t& lo) {
    __nv_bfloat16 h0 = __float2bfloat16_rn(x0);
    __nv_bfloat16 h1 = __float2bfloat16_rn(x1);
    float r0 = x0 - __bfloat162float(h0);
    float r1 = x1 - __bfloat162float(h1);
    __nv_bfloat16 l0 = __float2bfloat16_rn(r0);
    __nv_bfloat16 l1 = __float2bfloat16_rn(r1);
    hi = ((uint32_t)__bfloat16_as_ushort(h1) << 16) | __bfloat16_as_ushort(h0);
    lo = ((uint32_t)__bfloat16_as_ushort(l1) << 16) | __bfloat16_as_ushort(l0);
}

// pack two floats into f16x2 word (x0 -> low) + residual word
__device__ __forceinline__ void f16x2_split(float x0, float x1,
                                            uint32_t& hi, uint32_t& lo) {
    __half h0 = __float2half_rn(x0);
    __half h1 = __float2half_rn(x1);
    float r0 = x0 - __half2float(h0);
    float r1 = x1 - __half2float(h1);
    __half l0 = __float2half_rn(r0);
    __half l1 = __float2half_rn(r1);
    hi = ((uint32_t)__half_as_ushort(h1) << 16) | __half_as_ushort(h0);
    lo = ((uint32_t)__half_as_ushort(l1) << 16) | __half_as_ushort(l0);
}

// single-drop pack: two floats -> one f16x2 word (x0 low, x1 high)
__device__ __forceinline__ uint32_t f16x2_pack(float x0, float x1) {
    uint32_t w;
    asm("cvt.rn.f16x2.f32 %0, %1, %2;" : "=r"(w) : "f"(x1), "f"(x0));
    return w;
}

// ===========================================================================
// split kernels
// ===========================================================================
__global__ void split_kernel(const float* __restrict__ src,
                             uint32_t* __restrict__ hi,
                             uint32_t* __restrict__ lo, int n4)
{
    int i = blockIdx.x * blockDim.x + threadIdx.x;
    if (i >= n4) return;
    float4 v = ((const float4*)src)[i];
    uint32_t h0, l0, h1, l1;
    bf16x2_split(v.x, v.y, h0, l0);
    bf16x2_split(v.z, v.w, h1, l1);
    ((uint2*)hi)[i] = make_uint2(h0, h1);
    ((uint2*)lo)[i] = make_uint2(l0, l1);
}

__global__ void split_w4_kernel(const float* __restrict__ Wq,
                                const float* __restrict__ Wk,
                                const float* __restrict__ Wv,
                                const float* __restrict__ Wo,
                                uint32_t* __restrict__ wall_hi,
                                uint32_t* __restrict__ wall_lo,
                                uint32_t* __restrict__ wo_hi,
                                uint32_t* __restrict__ wo_lo,
                                int n4region)
{
    int gi = blockIdx.x * blockDim.x + threadIdx.x;
    int region = gi / n4region;
    int i = gi - region * n4region;
    const float* src = (region == 0) ? Wq : (region == 1) ? Wk
                     : (region == 2) ? Wv : Wo;
    uint32_t* hi = (region < 3) ? wall_hi + (size_t)region * 2 * n4region : wo_hi;
    uint32_t* lo = (region < 3) ? wall_lo + (size_t)region * 2 * n4region : wo_lo;
    float4 v = ((const float4*)src)[i];
    uint32_t h0, l0, h1, l1;
    bf16x2_split(v.x, v.y, h0, l0);
    bf16x2_split(v.z, v.w, h1, l1);
    ((uint2*)hi)[i] = make_uint2(h0, h1);
    ((uint2*)lo)[i] = make_uint2(l0, l1);
}

__global__ void bias3_kernel(const float* __restrict__ bq,
                             const float* __restrict__ bk,
                             const float* __restrict__ bv,
                             float* __restrict__ dst)
{
    int i = blockIdx.x * blockDim.x + threadIdx.x;
    if (i < kHID)              dst[i] = bq[i];
    else if (i < 2 * kHID)     dst[i] = bk[i - kHID];
    else if (i < 3 * kHID)     dst[i] = bv[i - 2 * kHID];
}

// ===========================================================================
// bf16x3 GEMM: cp.async 2-stage, 2 CTAs/SM, ldmatrix.
// Packed output can be bf16 hi/lo (f16out=0) or fp16 hi/lo (f16out=1).
// ===========================================================================
constexpr int GW    = 16;
constexpr int GSTR  = 20;
constexpr int GT    = 128 * GSTR;
constexpr int GSTAGE = 4 * GT;
constexpr int GEMM_SMEM = 2 * GSTAGE * 4;   // 81920 B

__global__ __launch_bounds__(256, 2)
void gemm_bf16x3(const uint32_t* __restrict__ Ah, const uint32_t* __restrict__ Al,
                 const uint32_t* __restrict__ Bh, const uint32_t* __restrict__ Bl,
                 const float* __restrict__ bias,
                 float* __restrict__ Cf,
                 uint32_t* __restrict__ Ch, uint32_t* __restrict__ Cl,
                 int M, int N, int K, int scaleCols, float scaleVal, int f16out)
{
    extern __shared__ uint32_t smw[];
    const uint32_t sb = smem_u32(smw);

    const int tid  = threadIdx.x;
    const int wid  = tid >> 5;
    const int lane = tid & 31;
    const int g    = lane >> 2;
    const int t    = lane & 3;

    const int wm = (wid & 3) * 32;
    const int wn = (wid >> 2) * 64;

    const int lm8 = lane & 7;
    const int lq  = lane >> 3;
    const int a_row = lm8 + (lq & 1) * 8;
    const int a_wof = (lq >> 1) * 4;
    const int b_row = lm8 + (lq >> 1) * 8;
    const int b_wof = (lq & 1) * 4;

    const int brow = blockIdx.y * 128;
    const int bcol = blockIdx.x * 128;
    const int kw   = K >> 1;
    const int nchunks = K / 32;

    const int lr0 = tid >> 2;
    const int lw4 = (tid & 3) * 4;

    float acc[2][8][4];
    #pragma unroll
    for (int mi = 0; mi < 2; mi++)
        #pragma unroll
        for (int nf = 0; nf < 8; nf++)
            #pragma unroll
            for (int j = 0; j < 4; j++) acc[mi][nf][j] = 0.f;

    auto cpa_chunk = [&](int c, int buf) {
        const uint32_t s = sb + (uint32_t)((buf * GSTAGE) << 2);
        const uint32_t* a_h = Ah + (size_t)brow * kw + c * GW + lw4;
        const uint32_t* a_l = Al + (size_t)brow * kw + c * GW + lw4;
        const uint32_t* b_h = Bh + (size_t)bcol * kw + c * GW + lw4;
        const uint32_t* b_l = Bl + (size_t)bcol * kw + c * GW + lw4;
        #pragma unroll
        for (int j = 0; j < 2; j++) {
            const int r = lr0 + 64 * j;
            const uint32_t d = (uint32_t)((r * GSTR + lw4) << 2);
            cp_async16(s + ((0 * GT) << 2) + d, a_h + (size_t)r * kw);
            cp_async16(s + ((1 * GT) << 2) + d, a_l + (size_t)r * kw);
            cp_async16(s + ((2 * GT) << 2) + d, b_h + (size_t)r * kw);
            cp_async16(s + ((3 * GT) << 2) + d, b_l + (size_t)r * kw);
        }
        cp_commit();
    };

    cpa_chunk(0, 0);

    for (int c = 0; c < nchunks; c++) {
        cp_wait0();
        __syncthreads();
        if (c + 1 < nchunks) cpa_chunk(c + 1, (c + 1) & 1);

        const uint32_t base = sb + (uint32_t)(((c & 1) * GSTAGE) << 2);

        #pragma unroll
        for (int kk = 0; kk < 2; kk++) {
            const int k0 = kk * 8;
            uint32_t aH[2][4], aL[2][4];
            #pragma unroll
            for (int mi = 0; mi < 2; mi++) {
                uint32_t arow = (uint32_t)((wm + mi * 16 + a_row) * GSTR + k0 + a_wof);
                ldsm_x4(aH[mi][0], aH[mi][1], aH[mi][2], aH[mi][3],
                        base + ((0 * GT + arow) << 2));
                ldsm_x4(aL[mi][0], aL[mi][1], aL[mi][2], aL[mi][3],
                        base + ((1 * GT + arow) << 2));
            }
            #pragma unroll
            for (int np = 0; np < 4; np++) {
                uint32_t nrow = (uint32_t)((wn + np * 16 + b_row) * GSTR + k0 + b_wof);
                uint32_t bh[4], bl[4];
                ldsm_x4(bh[0], bh[1], bh[2], bh[3], base + ((2 * GT + nrow) << 2));
                ldsm_x4(bl[0], bl[1], bl[2], bl[3], base + ((3 * GT + nrow) << 2));
                #pragma unroll
                for (int mi = 0; mi < 2; mi++)
                    #pragma unroll
                    for (int half = 0; half < 2; half++)
                        mma_bf16(acc[mi][np * 2 + half], aH[mi], bh + 2 * half);
                #pragma unroll
                for (int mi = 0; mi < 2; mi++)
                    #pragma unroll
                    for (int half = 0; half < 2; half++)
                        mma_bf16(acc[mi][np * 2 + half], aH[mi], bl + 2 * half);
                #pragma unroll
                for (int mi = 0; mi < 2; mi++)
                    #pragma unroll
                    for (int half = 0; half < 2; half++)
                        mma_bf16(acc[mi][np * 2 + half], aL[mi], bh + 2 * half);
            }
        }
    }

    const int nw = N >> 1;
    #pragma unroll
    for (int mi = 0; mi < 2; mi++) {
        const int r0 = brow + wm + mi * 16 + g;
        #pragma unroll
        for (int nf = 0; nf < 8; nf++) {
            const int c0 = bcol + wn + nf * 8 + 2 * t;
            float bx = bias[c0], by = bias[c0 + 1];
            float v0 = acc[mi][nf][0] + bx, v1 = acc[mi][nf][1] + by;
            float v2 = acc[mi][nf][2] + bx, v3 = acc[mi][nf][3] + by;
            if (Cf) {
                *(float2*)(Cf + (size_t)r0 * N + c0)       = make_float2(v0, v1);
                *(float2*)(Cf + (size_t)(r0 + 8) * N + c0) = make_float2(v2, v3);
            } else {
                float sc = (c0 < scaleCols) ? scaleVal : 1.0f;
                v0 *= sc; v1 *= sc; v2 *= sc; v3 *= sc;
                uint32_t h, l;
                if (f16out) f16x2_split(v0, v1, h, l);
                else        bf16x2_split(v0, v1, h, l);
                Ch[(size_t)r0 * nw + (c0 >> 1)] = h;
                Cl[(size_t)r0 * nw + (c0 >> 1)] = l;
                if (f16out) f16x2_split(v2, v3, h, l);
                else        bf16x2_split(v2, v3, h, l);
                Ch[(size_t)(r0 + 8) * nw + (c0 >> 1)] = h;
                Cl[(size_t)(r0 + 8) * nw + (c0 >> 1)] = l;
            }
        }
    }
}

// ===========================================================================
// fp16 2-term flash attention, 2 CTAs/SM, exp/PV interleave.
// QK: qH(f16) x (kH + kL)   -- 2 mma, q quant err 2^-11
// PV: p(f16)  x (vH + vL)   -- 2 mma, P quant err 2^-11
// Q staged hi-only; V [key][hd] + trans-ldmatrix; output ctx in bf16 hi/lo.
// ===========================================================================
constexpr int QSTR = 36;                     // padded word stride
constexpr int AT_Q  = 128 * QSTR;            // Q hi only
constexpr int AT_KV = 64 * QSTR;
constexpr int AT_STAGE = 4 * AT_KV;          // KH KL VH VL
constexpr int ATTN_SMEM = (AT_Q + 2 * AT_STAGE) * 4;  // 92,160 B

__global__ __launch_bounds__(256, 2)
void attn_f16(const uint32_t* __restrict__ Qh, const uint32_t* __restrict__ Ql,
              uint32_t* __restrict__ Oh, uint32_t* __restrict__ Ol)
{
    extern __shared__ uint32_t smw[];
    const uint32_t sb = smem_u32(smw);
    const uint32_t qhb = sb;                               // QH
    const uint32_t stg = qhb + (uint32_t)(AT_Q << 2);      // stages
    const uint32_t kvb = (uint32_t)(AT_KV << 2);

    const int tid  = threadIdx.x;
    const int w    = tid >> 5;
    const int lane = tid & 31;
    const int g    = lane >> 2;
    const int t    = lane & 3;

    const int lm8 = lane & 7;
    const int lq  = lane >> 3;
    const int a_row = lm8 + (lq & 1) * 8;
    const int a_wof = (lq >> 1) * 4;
    const int b_row = lm8 + (lq >> 1) * 8;
    const int b_wof = (lq & 1) * 4;
    const int v_row = lm8 + (lq & 1) * 8;
    const int v_wof = (lq >> 1) * 4;

    const int bh = blockIdx.y;
    const int b  = bh >> 4;
    const int h  = bh & 15;
    const int q0 = blockIdx.x * 128;

    const size_t rowbase = (size_t)(b * kS) * kQKVW;
    const int qoff = h * 32;
    const int koff = 512 + h * 32;
    const int voff = 1024 + h * 32;

    // ---- stage Q (hi only) via cp.async ----
    {
        #pragma unroll
        for (int i = 0; i < 4; i++) {
            int idx = tid + 256 * i;            // 0..1023
            int r   = idx >> 3;
            int ch  = (idx & 7) * 4;
            const uint32_t* src = Qh + rowbase
                                + (size_t)(q0 + r) * kQKVW + qoff + ch;
            cp_async16(qhb + (uint32_t)((r * QSTR + ch) << 2), src);
        }
        cp_commit();
    }

    float o[8][4];
    #pragma unroll
    for (int nf = 0; nf < 8; nf++)
        #pragma unroll
        for (int e = 0; e < 4; e++) o[nf][e] = 0.f;
    float lsum0 = 0.f, lsum1 = 0.f;

    auto cpa_tile = [&](int kt, int buf) {
        const uint32_t s = stg + (uint32_t)((buf * AT_STAGE) << 2);
        #pragma unroll
        for (int i = 0; i < 8; i++) {
            int idx = tid + 256 * i;            // 0..2047
            int arr = idx >> 9;                 // 0:KH 1:KL 2:VH 3:VL
            int rem = idx & 511;
            int key = rem >> 3;
            int ch  = (rem & 7) * 4;
            int off = (arr < 2) ? koff : voff;
            const uint32_t* base = ((arr & 1) ? Ql : Qh);
            const uint32_t* src = base + rowbase
                                + (size_t)(kt + key) * kQKVW + off + ch;
            uint32_t dst = s + (uint32_t)((arr * AT_KV + key * QSTR + ch) << 2);
            cp_async16(dst, src);
        }
        cp_commit();
    };

    cpa_tile(0, 0);

    for (int tI = 0; tI < kS / 64; tI++) {
        cp_wait0();
        __syncthreads();
        if (tI + 1 < kS / 64) cpa_tile((tI + 1) * 64, (tI + 1) & 1);

        const uint32_t stb = stg + (uint32_t)(((tI & 1) * AT_STAGE) << 2);

        // ---- S = qH (kH + kL), np-paired, term-major ----
        float s[8][4];
        #pragma unroll
        for (int nf = 0; nf < 8; nf++)
            s[nf][0] = s[nf][1] = s[nf][2] = s[nf][3] = 0.f;

        #pragma unroll
        for (int ks = 0; ks < 4; ks++) {
            const int k0 = ks * 8;
            uint32_t qH[4];
            uint32_t qrow = (uint32_t)(((w * 16 + a_row) * QSTR + k0 + a_wof) << 2);
            ldsm_x4(qH[0], qH[1], qH[2], qH[3], qhb + qrow);
            #pragma unroll
            for (int npp = 0; npp < 2; npp++) {
                uint32_t kh[2][4], kl[2][4];
                #pragma unroll
                for (int j = 0; j < 2; j++) {
                    const int np = npp * 2 + j;
                    uint32_t roff = (uint32_t)(((np * 16 + b_row) * QSTR + k0 + b_wof) << 2);
                    ldsm_x4(kh[j][0], kh[j][1], kh[j][2], kh[j][3], stb + roff);
                    ldsm_x4(kl[j][0], kl[j][1], kl[j][2], kl[j][3], stb + kvb + roff);
                }
                #pragma unroll
                for (int j = 0; j < 2; j++)
                    #pragma unroll
                    for (int half = 0; half < 2; half++)
                        mma_f16(s[npp * 4 + j * 2 + half], qH, kh[j] + 2 * half);
                #pragma unroll
                for (int j = 0; j < 2; j++)
                    #pragma unroll
                    for (int half = 0; half < 2; half++)
                        mma_f16(s[npp * 4 + j * 2 + half], qH, kl[j] + 2 * half);
            }
        }

        // ---- per-kc: exp + pack P (single f16) + PV mma ----
        #pragma unroll
        for (int kc = 0; kc < 4; kc++) {
            float p00 = __expf(s[2*kc][0]);
            float p01 = __expf(s[2*kc][1]);
            float p02 = __expf(s[2*kc][2]);
            float p03 = __expf(s[2*kc][3]);
            float p10 = __expf(s[2*kc+1][0]);
            float p11 = __expf(s[2*kc+1][1]);
            float p12 = __expf(s[2*kc+1][2]);
            float p13 = __expf(s[2*kc+1][3]);
            lsum0 += p00 + p01 + p10 + p11;
            lsum1 += p02 + p03 + p12 + p13;

            uint32_t pa[4];
            pa[0] = f16x2_pack(p00, p01);
            pa[1] = f16x2_pack(p02, p03);
            pa[2] = f16x2_pack(p10, p11);
            pa[3] = f16x2_pack(p12, p13);

            #pragma unroll
            for (int npp = 0; npp < 2; npp++) {
                uint32_t vh[2][4], vl[2][4];
                #pragma unroll
                for (int j = 0; j < 2; j++) {
                    const int np = npp * 2 + j;
                    uint32_t roff = (uint32_t)(
                        ((kc * 16 + v_row) * QSTR + np * 8 + v_wof) << 2);
                    ldsm_x4_t(vh[j][0], vh[j][1], vh[j][2], vh[j][3],
                              stb + 2 * kvb + roff);
                    ldsm_x4_t(vl[j][0], vl[j][1], vl[j][2], vl[j][3],
                              stb + 3 * kvb + roff);
                }
                #pragma unroll
                for (int j = 0; j < 2; j++)
                    #pragma unroll
                    for (int half = 0; half < 2; half++)
                        mma_f16(o[npp * 4 + j * 2 + half], pa, vh[j] + 2 * half);
                #pragma unroll
                for (int j = 0; j < 2; j++)
                    #pragma unroll
                    for (int half = 0; half < 2; half++)
                        mma_f16(o[npp * 4 + j * 2 + half], pa, vl[j] + 2 * half);
            }
        }
    }

    // ---- reduce, normalize, split-pack (bf16 for O GEMM), store ctx ----
    lsum0 += __shfl_xor_sync(0xFFFFFFFFu, lsum0, 1);
    lsum0 += __shfl_xor_sync(0xFFFFFFFFu, lsum0, 2);
    lsum1 += __shfl_xor_sync(0xFFFFFFFFu, lsum1, 1);
    lsum1 += __shfl_xor_sync(0xFFFFFFFFu, lsum1, 2);
    const float inv0 = 1.f / lsum0;
    const float inv1 = 1.f / lsum1;

    const size_t row0 = (size_t)(b * kS + q0 + w * 16 + g);
    #pragma unroll
    for (int nf = 0; nf < 8; nf++) {
        const int cw = h * 32 + nf * 4 + t;
        uint32_t hw, lw;
        bf16x2_split(o[nf][0] * inv0, o[nf][1] * inv0, hw, lw);
        Oh[row0 * kRW + cw] = hw;
        Ol[row0 * kRW + cw] = lw;
        bf16x2_split(o[nf][2] * inv1, o[nf][3] * inv1, hw, lw);
        Oh[(row0 + 8) * kRW + cw] = hw;
        Ol[(row0 + 8) * kRW + cw] = lw;
    }
}

// ===========================================================================
// launch
// ===========================================================================
extern "C" void kernel_launch(void* const* d_in, const int* in_sizes, int n_in,
                              void* d_out, int out_size)
{
    const float* x  = (const float*)d_in[0];
    const float* Wq = (const float*)d_in[1];
    const float* bq = (const float*)d_in[2];
    const float* Wk = (const float*)d_in[3];
    const float* bk = (const float*)d_in[4];
    const float* Wv = (const float*)d_in[5];
    const float* bv = (const float*)d_in[6];
    const float* Wo = (const float*)d_in[7];
    const float* bo = (const float*)d_in[8];
    float* out = (float*)d_out;

    uint32_t *xs_hi, *xs_lo, *wall_hi, *wall_lo, *wo_hi, *wo_lo;
    uint32_t *qkv_hi, *qkv_lo, *ctx_hi, *ctx_lo;
    float* bias_all;
    cudaGetSymbolAddress((void**)&xs_hi,   g_xs_hi);
    cudaGetSymbolAddress((void**)&xs_lo,   g_xs_lo);
    cudaGetSymbolAddress((void**)&wall_hi, g_wall_hi);
    cudaGetSymbolAddress((void**)&wall_lo, g_wall_lo);
    cudaGetSymbolAddress((void**)&wo_hi,   g_wo_hi);
    cudaGetSymbolAddress((void**)&wo_lo,   g_wo_lo);
    cudaGetSymbolAddress((void**)&bias_all,g_bias_all);
    cudaGetSymbolAddress((void**)&qkv_hi,  g_qkv_hi);
    cudaGetSymbolAddress((void**)&qkv_lo,  g_qkv_lo);
    cudaGetSymbolAddress((void**)&ctx_hi,  g_ctx_hi);
    cudaGetSymbolAddress((void**)&ctx_lo,  g_ctx_lo);

    cudaFuncSetAttribute(gemm_bf16x3,
                         cudaFuncAttributeMaxDynamicSharedMemorySize, GEMM_SMEM);
    cudaFuncSetAttribute(attn_f16,
                         cudaFuncAttributeMaxDynamicSharedMemorySize, ATTN_SMEM);

    const int wq4 = kHID * kD / 4;   // 262144
    split_kernel<<<kM * kD / 4 / 256, 256>>>(x, xs_hi, xs_lo, kM * kD / 4);
    split_w4_kernel<<<4 * wq4 / 256, 256>>>(Wq, Wk, Wv, Wo,
                                            wall_hi, wall_lo, wo_hi, wo_lo, wq4);
    bias3_kernel<<<12, 256>>>(bq, bk, bv, bias_all);

    // fused QKV projection (3-term): output packed as fp16 hi/lo; Q scaled 1/32
    dim3 gqkv(3 * kHID / 128, kM / 128);   // (24, 32)
    gemm_bf16x3<<<gqkv, 256, GEMM_SMEM>>>(
        xs_hi, xs_lo, wall_hi, wall_lo, bias_all,
        nullptr, qkv_hi, qkv_lo, kM, 3 * kHID, kD, kHID, kScale, 1);

    dim3 ga(kS / 128, kB * kH);            // (16, 32)
    attn_f16<<<ga, 256, ATTN_SMEM>>>(qkv_hi, qkv_lo, ctx_hi, ctx_lo);

    // output projection (3-term, bf16 path)
    dim3 go(kD / 128, kM / 128);           // (8, 32)
    gemm_bf16x3<<<go, 256, GEMM_SMEM>>>(
        ctx_hi, ctx_lo, wo_hi, wo_lo, bo,
        out, nullptr, nullptr, kM, kD, kHID, 0, 1.0f, 0);
}

// round 15
// speedup vs baseline: 1.5980x; 1.4011x over previous
#include <cuda_runtime.h>
#include <cuda_bf16.h>
#include <cuda_fp16.h>
#include <cstdint>
#include <cstddef>

// ===========================================================================
// Problem constants
// ===========================================================================
constexpr int kB   = 2;
constexpr int kS   = 2048;
constexpr int kD   = 1024;
constexpr int kHID = 1024;
constexpr int kH   = 16;
constexpr int kHD  = 64;
constexpr int kM   = kB * kS;      // 4096
constexpr float kScale = 0.03125f; // 1/sqrt(1024), exact power of two

constexpr int kRW   = kD / 2;      // 512 words per row (K=1024 packed)
constexpr int kQKVW = 3 * kRW;     // 1536 words per qkv row

// ===========================================================================
// Scratch (device globals; allocation-free rule)
// ===========================================================================
__device__ uint32_t g_xs_hi [(size_t)kM * kRW];           // fp16 pairs
__device__ uint32_t g_wall_hi[(size_t)3 * kHID * kRW];    // fp16 pairs
__device__ uint32_t g_wall_lo[(size_t)3 * kHID * kRW];    // fp16 pairs
__device__ uint32_t g_wo_hi [(size_t)kD * kRW];           // bf16 pairs
__device__ uint32_t g_wo_lo [(size_t)kD * kRW];           // bf16 pairs
__device__ float    g_bias_all[3 * kHID];
__device__ uint32_t g_qkv_hi[(size_t)kM * kQKVW];         // fp16 pairs
__device__ uint32_t g_ctx_hi[(size_t)kM * kRW];           // bf16 pairs
__device__ uint32_t g_ctx_lo[(size_t)kM * kRW];           // bf16 pairs

// ===========================================================================
// helpers
// ===========================================================================
__device__ __forceinline__ void mma_bf16(float* d, const uint32_t* a, const uint32_t* b) {
    asm volatile(
        "mma.sync.aligned.m16n8k16.row.col.f32.bf16.bf16.f32 "
        "{%0,%1,%2,%3}, {%4,%5,%6,%7}, {%8,%9}, {%0,%1,%2,%3};"
        : "+f"(d[0]), "+f"(d[1]), "+f"(d[2]), "+f"(d[3])
        : "r"(a[0]), "r"(a[1]), "r"(a[2]), "r"(a[3]),
          "r"(b[0]), "r"(b[1]));
}

__device__ __forceinline__ void mma_f16(float* d, const uint32_t* a, const uint32_t* b) {
    asm volatile(
        "mma.sync.aligned.m16n8k16.row.col.f32.f16.f16.f32 "
        "{%0,%1,%2,%3}, {%4,%5,%6,%7}, {%8,%9}, {%0,%1,%2,%3};"
        : "+f"(d[0]), "+f"(d[1]), "+f"(d[2]), "+f"(d[3])
        : "r"(a[0]), "r"(a[1]), "r"(a[2]), "r"(a[3]),
          "r"(b[0]), "r"(b[1]));
}

__device__ __forceinline__ void ldsm_x4(uint32_t& r0, uint32_t& r1,
                                        uint32_t& r2, uint32_t& r3, uint32_t addr) {
    asm volatile(
        "ldmatrix.sync.aligned.m8n8.x4.shared.b16 {%0,%1,%2,%3}, [%4];"
        : "=r"(r0), "=r"(r1), "=r"(r2), "=r"(r3) : "r"(addr));
}

__device__ __forceinline__ void ldsm_x4_t(uint32_t& r0, uint32_t& r1,
                                          uint32_t& r2, uint32_t& r3, uint32_t addr) {
    asm volatile(
        "ldmatrix.sync.aligned.m8n8.x4.trans.shared.b16 {%0,%1,%2,%3}, [%4];"
        : "=r"(r0), "=r"(r1), "=r"(r2), "=r"(r3) : "r"(addr));
}

__device__ __forceinline__ uint32_t smem_u32(const void* p) {
    uint32_t a;
    asm("{ .reg .u64 t; cvta.to.shared.u64 t, %1; cvt.u32.u64 %0, t; }"
        : "=r"(a) : "l"(p));
    return a;
}

__device__ __forceinline__ void cp_async16(uint32_t smem_addr, const void* gmem) {
    asm volatile("cp.async.cg.shared.global [%0], [%1], 16;"
                 :: "r"(smem_addr), "l"(gmem));
}
__device__ __forceinline__ void cp_commit() {
    asm volatile("cp.async.commit_group;");
}
__device__ __forceinline__ void cp_wait0() {
    asm volatile("cp.async.wait_group 0;");
}

__device__ __forceinline__ void bf16x2_split(float x0, float x1,
                                             uint32_t& hi, uint32_t& lo) {
    __nv_bfloat16 h0 = __float2bfloat16_rn(x0);
    __nv_bfloat16 h1 = __float2bfloat16_rn(x1);
    float r0 = x0 - __bfloat162float(h0);
    float r1 = x1 - __bfloat162float(h1);
    __nv_bfloat16 l0 = __float2bfloat16_rn(r0);
    __nv_bfloat16 l1 = __float2bfloat16_rn(r1);
    hi = ((uint32_t)__bfloat16_as_ushort(h1) << 16) | __bfloat16_as_ushort(h0);
    lo = ((uint32_t)__bfloat16_as_ushort(l1) << 16) | __bfloat16_as_ushort(l0);
}

__device__ __forceinline__ void f16x2_split(float x0, float x1,
                                            uint32_t& hi, uint32_t& lo) {
    __half h0 = __float2half_rn(x0);
    __half h1 = __float2half_rn(x1);
    float r0 = x0 - __half2float(h0);
    float r1 = x1 - __half2float(h1);
    __half l0 = __float2half_rn(r0);
    __half l1 = __float2half_rn(r1);
    hi = ((uint32_t)__half_as_ushort(h1) << 16) | __half_as_ushort(h0);
    lo = ((uint32_t)__half_as_ushort(l1) << 16) | __half_as_ushort(l0);
}

__device__ __forceinline__ uint32_t f16x2_pack(float x0, float x1) {
    uint32_t w;
    asm("cvt.rn.f16x2.f32 %0, %1, %2;" : "=r"(w) : "f"(x1), "f"(x0));
    return w;
}

// ===========================================================================
// split kernels
// ===========================================================================
// x -> fp16 hi only
__global__ void split_x_f16hi(const float* __restrict__ src,
                              uint32_t* __restrict__ hi, int n4)
{
    int i = blockIdx.x * blockDim.x + threadIdx.x;
    if (i >= n4) return;
    float4 v = ((const float4*)src)[i];
    ((uint2*)hi)[i] = make_uint2(f16x2_pack(v.x, v.y), f16x2_pack(v.z, v.w));
}

// Wq/Wk/Wv -> fp16 hi/lo into wall; Wo -> bf16 hi/lo into wo
__global__ void split_w4_kernel(const float* __restrict__ Wq,
                                const float* __restrict__ Wk,
                                const float* __restrict__ Wv,
                                const float* __restrict__ Wo,
                                uint32_t* __restrict__ wall_hi,
                                uint32_t* __restrict__ wall_lo,
                                uint32_t* __restrict__ wo_hi,
                                uint32_t* __restrict__ wo_lo,
                                int n4region)
{
    int gi = blockIdx.x * blockDim.x + threadIdx.x;
    int region = gi / n4region;
    int i = gi - region * n4region;
    const float* src = (region == 0) ? Wq : (region == 1) ? Wk
                     : (region == 2) ? Wv : Wo;
    float4 v = ((const float4*)src)[i];
    uint32_t h0, l0, h1, l1;
    if (region < 3) {
        f16x2_split(v.x, v.y, h0, l0);
        f16x2_split(v.z, v.w, h1, l1);
        uint32_t* hi = wall_hi + (size_t)region * 2 * n4region;
        uint32_t* lo = wall_lo + (size_t)region * 2 * n4region;
        ((uint2*)hi)[i] = make_uint2(h0, h1);
        ((uint2*)lo)[i] = make_uint2(l0, l1);
    } else {
        bf16x2_split(v.x, v.y, h0, l0);
        bf16x2_split(v.z, v.w, h1, l1);
        ((uint2*)wo_hi)[i] = make_uint2(h0, h1);
        ((uint2*)wo_lo)[i] = make_uint2(l0, l1);
    }
}

__global__ void bias3_kernel(const float* __restrict__ bq,
                             const float* __restrict__ bk,
                             const float* __restrict__ bv,
                             float* __restrict__ dst)
{
    int i = blockIdx.x * blockDim.x + threadIdx.x;
    if (i < kHID)              dst[i] = bq[i];
    else if (i < 2 * kHID)     dst[i] = bk[i - kHID];
    else if (i < 3 * kHID)     dst[i] = bv[i - 2 * kHID];
}

// ===========================================================================
// GEMM, templated:
//  MODE=0: bf16 3-term (aH bH + aH bL + aL bH), A hi+lo, fp32 out
//  MODE=1: fp16 2-term (aH bH + aH bL),          A hi only, packed fp16 out
// cp.async 2-stage, 2 CTAs/SM, ldmatrix fragments.
// ===========================================================================
constexpr int GW    = 16;
constexpr int GSTR  = 20;
constexpr int GT    = 128 * GSTR;
constexpr int GEMM_SMEM3 = 2 * 4 * GT * 4;   // 81920 B
constexpr int GEMM_SMEM2 = 2 * 3 * GT * 4;   // 61440 B

template <int MODE>
__global__ __launch_bounds__(256, 2)
void gemm_split(const uint32_t* __restrict__ Ah, const uint32_t* __restrict__ Al,
                const uint32_t* __restrict__ Bh, const uint32_t* __restrict__ Bl,
                const float* __restrict__ bias,
                float* __restrict__ Cf,
                uint32_t* __restrict__ Ch,
                int M, int N, int K, int scaleCols, float scaleVal)
{
    extern __shared__ uint32_t smw[];
    constexpr int NARR = (MODE == 0) ? 4 : 3;
    constexpr int GSTAGE = NARR * GT;
    const uint32_t sb = smem_u32(smw);

    const int tid  = threadIdx.x;
    const int wid  = tid >> 5;
    const int lane = tid & 31;
    const int g    = lane >> 2;
    const int t    = lane & 3;

    const int wm = (wid & 3) * 32;
    const int wn = (wid >> 2) * 64;

    const int lm8 = lane & 7;
    const int lq  = lane >> 3;
    const int a_row = lm8 + (lq & 1) * 8;
    const int a_wof = (lq >> 1) * 4;
    const int b_row = lm8 + (lq >> 1) * 8;
    const int b_wof = (lq & 1) * 4;

    const int brow = blockIdx.y * 128;
    const int bcol = blockIdx.x * 128;
    const int kw   = K >> 1;
    const int nchunks = K / 32;

    const int lr0 = tid >> 2;
    const int lw4 = (tid & 3) * 4;

    float acc[2][8][4];
    #pragma unroll
    for (int mi = 0; mi < 2; mi++)
        #pragma unroll
        for (int nf = 0; nf < 8; nf++)
            #pragma unroll
            for (int j = 0; j < 4; j++) acc[mi][nf][j] = 0.f;

    auto cpa_chunk = [&](int c, int buf) {
        const uint32_t s = sb + (uint32_t)((buf * GSTAGE) << 2);
        const uint32_t* a_h = Ah + (size_t)brow * kw + c * GW + lw4;
        const uint32_t* b_h = Bh + (size_t)bcol * kw + c * GW + lw4;
        const uint32_t* b_l = Bl + (size_t)bcol * kw + c * GW + lw4;
        #pragma unroll
        for (int j = 0; j < 2; j++) {
            const int r = lr0 + 64 * j;
            const uint32_t d = (uint32_t)((r * GSTR + lw4) << 2);
            cp_async16(s + ((0 * GT) << 2) + d, a_h + (size_t)r * kw);
            if (MODE == 0) {
                const uint32_t* a_l = Al + (size_t)brow * kw + c * GW + lw4;
                cp_async16(s + ((1 * GT) << 2) + d, a_l + (size_t)r * kw);
            }
            cp_async16(s + (((NARR - 2) * GT) << 2) + d, b_h + (size_t)r * kw);
            cp_async16(s + (((NARR - 1) * GT) << 2) + d, b_l + (size_t)r * kw);
        }
        cp_commit();
    };

    cpa_chunk(0, 0);

    for (int c = 0; c < nchunks; c++) {
        cp_wait0();
        __syncthreads();
        if (c + 1 < nchunks) cpa_chunk(c + 1, (c + 1) & 1);

        const uint32_t base = sb + (uint32_t)(((c & 1) * GSTAGE) << 2);

        #pragma unroll
        for (int kk = 0; kk < 2; kk++) {
            const int k0 = kk * 8;
            uint32_t aH[2][4], aL[2][4];
            #pragma unroll
            for (int mi = 0; mi < 2; mi++) {
                uint32_t arow = (uint32_t)((wm + mi * 16 + a_row) * GSTR + k0 + a_wof);
                ldsm_x4(aH[mi][0], aH[mi][1], aH[mi][2], aH[mi][3],
                        base + ((0 * GT + arow) << 2));
                if (MODE == 0)
                    ldsm_x4(aL[mi][0], aL[mi][1], aL[mi][2], aL[mi][3],
                            base + ((1 * GT + arow) << 2));
            }
            #pragma unroll
            for (int np = 0; np < 4; np++) {
                uint32_t nrow = (uint32_t)((wn + np * 16 + b_row) * GSTR + k0 + b_wof);
                uint32_t bh[4], bl[4];
                ldsm_x4(bh[0], bh[1], bh[2], bh[3],
                        base + (((NARR - 2) * GT + nrow) << 2));
                ldsm_x4(bl[0], bl[1], bl[2], bl[3],
                        base + (((NARR - 1) * GT + nrow) << 2));
                if (MODE == 0) {
                    #pragma unroll
                    for (int mi = 0; mi < 2; mi++)
                        #pragma unroll
                        for (int half = 0; half < 2; half++)
                            mma_bf16(acc[mi][np * 2 + half], aH[mi], bh + 2 * half);
                    #pragma unroll
                    for (int mi = 0; mi < 2; mi++)
                        #pragma unroll
                        for (int half = 0; half < 2; half++)
                            mma_bf16(acc[mi][np * 2 + half], aH[mi], bl + 2 * half);
                    #pragma unroll
                    for (int mi = 0; mi < 2; mi++)
                        #pragma unroll
                        for (int half = 0; half < 2; half++)
                            mma_bf16(acc[mi][np * 2 + half], aL[mi], bh + 2 * half);
                } else {
                    #pragma unroll
                    for (int mi = 0; mi < 2; mi++)
                        #pragma unroll
                        for (int half = 0; half < 2; half++)
                            mma_f16(acc[mi][np * 2 + half], aH[mi], bh + 2 * half);
                    #pragma unroll
                    for (int mi = 0; mi < 2; mi++)
                        #pragma unroll
                        for (int half = 0; half < 2; half++)
                            mma_f16(acc[mi][np * 2 + half], aH[mi], bl + 2 * half);
                }
            }
        }
    }

    const int nw = N >> 1;
    #pragma unroll
    for (int mi = 0; mi < 2; mi++) {
        const int r0 = brow + wm + mi * 16 + g;
        #pragma unroll
        for (int nf = 0; nf < 8; nf++) {
            const int c0 = bcol + wn + nf * 8 + 2 * t;
            float bx = bias[c0], by = bias[c0 + 1];
            float v0 = acc[mi][nf][0] + bx, v1 = acc[mi][nf][1] + by;
            float v2 = acc[mi][nf][2] + bx, v3 = acc[mi][nf][3] + by;
            if (MODE == 0) {
                *(float2*)(Cf + (size_t)r0 * N + c0)       = make_float2(v0, v1);
                *(float2*)(Cf + (size_t)(r0 + 8) * N + c0) = make_float2(v2, v3);
            } else {
                float sc = (c0 < scaleCols) ? scaleVal : 1.0f;
                Ch[(size_t)r0 * nw + (c0 >> 1)]       = f16x2_pack(v0 * sc, v1 * sc);
                Ch[(size_t)(r0 + 8) * nw + (c0 >> 1)] = f16x2_pack(v2 * sc, v3 * sc);
            }
        }
    }
}

// ===========================================================================
// fp16 1-term flash attention, 2 CTAs/SM, exp/PV interleave.
// QK: qH x kH   (1 mma) ; PV: p x vH (1 mma).
// K/V staged hi-only (smem 55 KB); V [key][hd] + trans-ldmatrix.
// Output ctx in bf16 hi/lo for the bf16x3 O projection.
// ===========================================================================
constexpr int QSTR = 36;
constexpr int AT_Q  = 128 * QSTR;            // Q hi only (4608 words)
constexpr int AT_KV = 64 * QSTR;             // 2304 words
constexpr int AT_STAGE = 2 * AT_KV;          // KH VH
constexpr int ATTN_SMEM = (AT_Q + 2 * AT_STAGE) * 4;  // 55,296 B

__global__ __launch_bounds__(256, 2)
void attn_f16(const uint32_t* __restrict__ Qh,
              uint32_t* __restrict__ Oh, uint32_t* __restrict__ Ol)
{
    extern __shared__ uint32_t smw[];
    const uint32_t sb = smem_u32(smw);
    const uint32_t qhb = sb;
    const uint32_t stg = qhb + (uint32_t)(AT_Q << 2);
    const uint32_t kvb = (uint32_t)(AT_KV << 2);

    const int tid  = threadIdx.x;
    const int w    = tid >> 5;
    const int lane = tid & 31;
    const int g    = lane >> 2;
    const int t    = lane & 3;

    const int lm8 = lane & 7;
    const int lq  = lane >> 3;
    const int a_row = lm8 + (lq & 1) * 8;
    const int a_wof = (lq >> 1) * 4;
    const int b_row = lm8 + (lq >> 1) * 8;
    const int b_wof = (lq & 1) * 4;
    const int v_row = lm8 + (lq & 1) * 8;
    const int v_wof = (lq >> 1) * 4;

    const int bh = blockIdx.y;
    const int b  = bh >> 4;
    const int h  = bh & 15;
    const int q0 = blockIdx.x * 128;

    const size_t rowbase = (size_t)(b * kS) * kQKVW;
    const int qoff = h * 32;
    const int koff = 512 + h * 32;
    const int voff = 1024 + h * 32;

    // ---- stage Q (hi only) ----
    {
        #pragma unroll
        for (int i = 0; i < 4; i++) {
            int idx = tid + 256 * i;
            int r   = idx >> 3;
            int ch  = (idx & 7) * 4;
            const uint32_t* src = Qh + rowbase
                                + (size_t)(q0 + r) * kQKVW + qoff + ch;
            cp_async16(qhb + (uint32_t)((r * QSTR + ch) << 2), src);
        }
        cp_commit();
    }

    float o[8][4];
    #pragma unroll
    for (int nf = 0; nf < 8; nf++)
        #pragma unroll
        for (int e = 0; e < 4; e++) o[nf][e] = 0.f;
    float lsum0 = 0.f, lsum1 = 0.f;

    auto cpa_tile = [&](int kt, int buf) {
        const uint32_t s = stg + (uint32_t)((buf * AT_STAGE) << 2);
        #pragma unroll
        for (int i = 0; i < 4; i++) {
            int idx = tid + 256 * i;            // 0..1023
            int arr = idx >> 9;                 // 0:KH 1:VH
            int rem = idx & 511;
            int key = rem >> 3;
            int ch  = (rem & 7) * 4;
            int off = arr ? voff : koff;
            const uint32_t* src = Qh + rowbase
                                + (size_t)(kt + key) * kQKVW + off + ch;
            uint32_t dst = s + (uint32_t)((arr * AT_KV + key * QSTR + ch) << 2);
            cp_async16(dst, src);
        }
        cp_commit();
    };

    cpa_tile(0, 0);

    for (int tI = 0; tI < kS / 64; tI++) {
        cp_wait0();
        __syncthreads();
        if (tI + 1 < kS / 64) cpa_tile((tI + 1) * 64, (tI + 1) & 1);

        const uint32_t stb = stg + (uint32_t)(((tI & 1) * AT_STAGE) << 2);

        // ---- S = qH kH (1-term) ----
        float s[8][4];
        #pragma unroll
        for (int nf = 0; nf < 8; nf++)
            s[nf][0] = s[nf][1] = s[nf][2] = s[nf][3] = 0.f;

        #pragma unroll
        for (int ks = 0; ks < 4; ks++) {
            const int k0 = ks * 8;
            uint32_t qH[4];
            uint32_t qrow = (uint32_t)(((w * 16 + a_row) * QSTR + k0 + a_wof) << 2);
            ldsm_x4(qH[0], qH[1], qH[2], qH[3], qhb + qrow);
            #pragma unroll
            for (int npp = 0; npp < 2; npp++) {
                uint32_t kh[2][4];
                #pragma unroll
                for (int j = 0; j < 2; j++) {
                    const int np = npp * 2 + j;
                    uint32_t roff = (uint32_t)(((np * 16 + b_row) * QSTR + k0 + b_wof) << 2);
                    ldsm_x4(kh[j][0], kh[j][1], kh[j][2], kh[j][3], stb + roff);
                }
                #pragma unroll
                for (int j = 0; j < 2; j++)
                    #pragma unroll
                    for (int half = 0; half < 2; half++)
                        mma_f16(s[npp * 4 + j * 2 + half], qH, kh[j] + 2 * half);
            }
        }

        // ---- per-kc: exp + pack + PV (1-term) ----
        #pragma unroll
        for (int kc = 0; kc < 4; kc++) {
            float p00 = __expf(s[2*kc][0]);
            float p01 = __expf(s[2*kc][1]);
            float p02 = __expf(s[2*kc][2]);
            float p03 = __expf(s[2*kc][3]);
            float p10 = __expf(s[2*kc+1][0]);
            float p11 = __expf(s[2*kc+1][1]);
            float p12 = __expf(s[2*kc+1][2]);
            float p13 = __expf(s[2*kc+1][3]);
            lsum0 += p00 + p01 + p10 + p11;
            lsum1 += p02 + p03 + p12 + p13;

            uint32_t pa[4];
            pa[0] = f16x2_pack(p00, p01);
            pa[1] = f16x2_pack(p02, p03);
            pa[2] = f16x2_pack(p10, p11);
            pa[3] = f16x2_pack(p12, p13);

            #pragma unroll
            for (int npp = 0; npp < 2; npp++) {
                uint32_t vh[2][4];
                #pragma unroll
                for (int j = 0; j < 2; j++) {
                    const int np = npp * 2 + j;
                    uint32_t roff = (uint32_t)(
                        ((kc * 16 + v_row) * QSTR + np * 8 + v_wof) << 2);
                    ldsm_x4_t(vh[j][0], vh[j][1], vh[j][2], vh[j][3],
                              stb + kvb + roff);
                }
                #pragma unroll
                for (int j = 0; j < 2; j++)
                    #pragma unroll
                    for (int half = 0; half < 2; half++)
                        mma_f16(o[npp * 4 + j * 2 + half], pa, vh[j] + 2 * half);
            }
        }
    }

    // ---- reduce, normalize, split-pack (bf16), store ctx ----
    lsum0 += __shfl_xor_sync(0xFFFFFFFFu, lsum0, 1);
    lsum0 += __shfl_xor_sync(0xFFFFFFFFu, lsum0, 2);
    lsum1 += __shfl_xor_sync(0xFFFFFFFFu, lsum1, 1);
    lsum1 += __shfl_xor_sync(0xFFFFFFFFu, lsum1, 2);
    const float inv0 = 1.f / lsum0;
    const float inv1 = 1.f / lsum1;

    const size_t row0 = (size_t)(b * kS + q0 + w * 16 + g);
    #pragma unroll
    for (int nf = 0; nf < 8; nf++) {
        const int cw = h * 32 + nf * 4 + t;
        uint32_t hw, lw;
        bf16x2_split(o[nf][0] * inv0, o[nf][1] * inv0, hw, lw);
        Oh[row0 * kRW + cw] = hw;
        Ol[row0 * kRW + cw] = lw;
        bf16x2_split(o[nf][2] * inv1, o[nf][3] * inv1, hw, lw);
        Oh[(row0 + 8) * kRW + cw] = hw;
        Ol[(row0 + 8) * kRW + cw] = lw;
    }
}

// ===========================================================================
// launch
// ===========================================================================
extern "C" void kernel_launch(void* const* d_in, const int* in_sizes, int n_in,
                              void* d_out, int out_size)
{
    const float* x  = (const float*)d_in[0];
    const float* Wq = (const float*)d_in[1];
    const float* bq = (const float*)d_in[2];
    const float* Wk = (const float*)d_in[3];
    const float* bk = (const float*)d_in[4];
    const float* Wv = (const float*)d_in[5];
    const float* bv = (const float*)d_in[6];
    const float* Wo = (const float*)d_in[7];
    const float* bo = (const float*)d_in[8];
    float* out = (float*)d_out;

    uint32_t *xs_hi, *wall_hi, *wall_lo, *wo_hi, *wo_lo;
    uint32_t *qkv_hi, *ctx_hi, *ctx_lo;
    float* bias_all;
    cudaGetSymbolAddress((void**)&xs_hi,   g_xs_hi);
    cudaGetSymbolAddress((void**)&wall_hi, g_wall_hi);
    cudaGetSymbolAddress((void**)&wall_lo, g_wall_lo);
    cudaGetSymbolAddress((void**)&wo_hi,   g_wo_hi);
    cudaGetSymbolAddress((void**)&wo_lo,   g_wo_lo);
    cudaGetSymbolAddress((void**)&bias_all,g_bias_all);
    cudaGetSymbolAddress((void**)&qkv_hi,  g_qkv_hi);
    cudaGetSymbolAddress((void**)&ctx_hi,  g_ctx_hi);
    cudaGetSymbolAddress((void**)&ctx_lo,  g_ctx_lo);

    cudaFuncSetAttribute(gemm_split<0>,
                         cudaFuncAttributeMaxDynamicSharedMemorySize, GEMM_SMEM3);
    cudaFuncSetAttribute(gemm_split<1>,
                         cudaFuncAttributeMaxDynamicSharedMemorySize, GEMM_SMEM2);
    cudaFuncSetAttribute(attn_f16,
                         cudaFuncAttributeMaxDynamicSharedMemorySize, ATTN_SMEM);

    const int wq4 = kHID * kD / 4;   // 262144
    split_x_f16hi<<<kM * kD / 4 / 256, 256>>>(x, xs_hi, kM * kD / 4);
    split_w4_kernel<<<4 * wq4 / 256, 256>>>(Wq, Wk, Wv, Wo,
                                            wall_hi, wall_lo, wo_hi, wo_lo, wq4);
    bias3_kernel<<<12, 256>>>(bq, bk, bv, bias_all);

    // fused QKV projection (fp16 2-term): M=4096, N=3072; Q scaled 1/32;
    // output packed fp16 hi-only (attention is 1-term)
    dim3 gqkv(3 * kHID / 128, kM / 128);   // (24, 32)
    gemm_split<1><<<gqkv, 256, GEMM_SMEM2>>>(
        xs_hi, nullptr, wall_hi, wall_lo, bias_all,
        nullptr, qkv_hi, kM, 3 * kHID, kD, kHID, kScale);

    dim3 ga(kS / 128, kB * kH);            // (16, 32)
    attn_f16<<<ga, 256, ATTN_SMEM>>>(qkv_hi, ctx_hi, ctx_lo);

    // output projection (bf16 3-term)
    dim3 go(kD / 128, kM / 128);           // (8, 32)
    gemm_split<0><<<go, 256, GEMM_SMEM3>>>(
        ctx_hi, ctx_lo, wo_hi, wo_lo, bo,
        out, nullptr, kM, kD, kHID, 0, 1.0f);
}

// round 16
// speedup vs baseline: 2.1340x; 1.3354x over previous
#include <cuda_runtime.h>
#include <cuda_bf16.h>
#include <cuda_fp16.h>
#include <cstdint>
#include <cstddef>

// ===========================================================================
// Problem constants
// ===========================================================================
constexpr int kB   = 2;
constexpr int kS   = 2048;
constexpr int kD   = 1024;
constexpr int kHID = 1024;
constexpr int kH   = 16;
constexpr int kHD  = 64;
constexpr int kM   = kB * kS;      // 4096
constexpr float kScale = 0.03125f; // 1/sqrt(1024), exact power of two

constexpr int kRW   = kD / 2;      // 512 words per row (K=1024 packed)
constexpr int kQKVW = 3 * kRW;     // 1536 words per qkv row

// ===========================================================================
// Scratch (device globals; allocation-free rule)
// ===========================================================================
__device__ uint32_t g_xs_hi [(size_t)kM * kRW];           // fp16 pairs
__device__ uint32_t g_wall_hi[(size_t)3 * kHID * kRW];    // fp16 pairs
__device__ uint32_t g_wo_hi [(size_t)kD * kRW];           // fp16 pairs
__device__ uint32_t g_wo_lo [(size_t)kD * kRW];           // fp16 pairs
__device__ float    g_bias_all[3 * kHID];
__device__ uint32_t g_qkv_hi[(size_t)kM * kQKVW];         // fp16 pairs
__device__ uint32_t g_ctx_hi[(size_t)kM * kRW];           // fp16 pairs

// ===========================================================================
// helpers
// ===========================================================================
__device__ __forceinline__ void mma_f16(float* d, const uint32_t* a, const uint32_t* b) {
    asm volatile(
        "mma.sync.aligned.m16n8k16.row.col.f32.f16.f16.f32 "
        "{%0,%1,%2,%3}, {%4,%5,%6,%7}, {%8,%9}, {%0,%1,%2,%3};"
        : "+f"(d[0]), "+f"(d[1]), "+f"(d[2]), "+f"(d[3])
        : "r"(a[0]), "r"(a[1]), "r"(a[2]), "r"(a[3]),
          "r"(b[0]), "r"(b[1]));
}

__device__ __forceinline__ void ldsm_x4(uint32_t& r0, uint32_t& r1,
                                        uint32_t& r2, uint32_t& r3, uint32_t addr) {
    asm volatile(
        "ldmatrix.sync.aligned.m8n8.x4.shared.b16 {%0,%1,%2,%3}, [%4];"
        : "=r"(r0), "=r"(r1), "=r"(r2), "=r"(r3) : "r"(addr));
}

__device__ __forceinline__ void ldsm_x4_t(uint32_t& r0, uint32_t& r1,
                                          uint32_t& r2, uint32_t& r3, uint32_t addr) {
    asm volatile(
        "ldmatrix.sync.aligned.m8n8.x4.trans.shared.b16 {%0,%1,%2,%3}, [%4];"
        : "=r"(r0), "=r"(r1), "=r"(r2), "=r"(r3) : "r"(addr));
}

__device__ __forceinline__ uint32_t smem_u32(const void* p) {
    uint32_t a;
    asm("{ .reg .u64 t; cvta.to.shared.u64 t, %1; cvt.u32.u64 %0, t; }"
        : "=r"(a) : "l"(p));
    return a;
}

__device__ __forceinline__ void cp_async16(uint32_t smem_addr, const void* gmem) {
    asm volatile("cp.async.cg.shared.global [%0], [%1], 16;"
                 :: "r"(smem_addr), "l"(gmem));
}
__device__ __forceinline__ void cp_commit() {
    asm volatile("cp.async.commit_group;");
}
__device__ __forceinline__ void cp_wait0() {
    asm volatile("cp.async.wait_group 0;");
}

__device__ __forceinline__ void f16x2_split(float x0, float x1,
                                            uint32_t& hi, uint32_t& lo) {
    __half h0 = __float2half_rn(x0);
    __half h1 = __float2half_rn(x1);
    float r0 = x0 - __half2float(h0);
    float r1 = x1 - __half2float(h1);
    __half l0 = __float2half_rn(r0);
    __half l1 = __float2half_rn(r1);
    hi = ((uint32_t)__half_as_ushort(h1) << 16) | __half_as_ushort(h0);
    lo = ((uint32_t)__half_as_ushort(l1) << 16) | __half_as_ushort(l0);
}

__device__ __forceinline__ uint32_t f16x2_pack(float x0, float x1) {
    uint32_t w;
    asm("cvt.rn.f16x2.f32 %0, %1, %2;" : "=r"(w) : "f"(x1), "f"(x0));
    return w;
}

// ===========================================================================
// split kernels
// ===========================================================================
// x -> fp16 hi only
__global__ void split_x_f16hi(const float* __restrict__ src,
                              uint32_t* __restrict__ hi, int n4)
{
    int i = blockIdx.x * blockDim.x + threadIdx.x;
    if (i >= n4) return;
    float4 v = ((const float4*)src)[i];
    ((uint2*)hi)[i] = make_uint2(f16x2_pack(v.x, v.y), f16x2_pack(v.z, v.w));
}

// Wq/Wk/Wv -> fp16 hi only into wall; Wo -> fp16 hi/lo into wo
__global__ void split_w4_kernel(const float* __restrict__ Wq,
                                const float* __restrict__ Wk,
                                const float* __restrict__ Wv,
                                const float* __restrict__ Wo,
                                uint32_t* __restrict__ wall_hi,
                                uint32_t* __restrict__ wo_hi,
                                uint32_t* __restrict__ wo_lo,
                                int n4region)
{
    int gi = blockIdx.x * blockDim.x + threadIdx.x;
    int region = gi / n4region;
    int i = gi - region * n4region;
    const float* src = (region == 0) ? Wq : (region == 1) ? Wk
                     : (region == 2) ? Wv : Wo;
    float4 v = ((const float4*)src)[i];
    if (region < 3) {
        uint32_t* hi = wall_hi + (size_t)region * 2 * n4region;
        ((uint2*)hi)[i] = make_uint2(f16x2_pack(v.x, v.y), f16x2_pack(v.z, v.w));
    } else {
        uint32_t h0, l0, h1, l1;
        f16x2_split(v.x, v.y, h0, l0);
        f16x2_split(v.z, v.w, h1, l1);
        ((uint2*)wo_hi)[i] = make_uint2(h0, h1);
        ((uint2*)wo_lo)[i] = make_uint2(l0, l1);
    }
}

__global__ void bias3_kernel(const float* __restrict__ bq,
                             const float* __restrict__ bk,
                             const float* __restrict__ bv,
                             float* __restrict__ dst)
{
    int i = blockIdx.x * blockDim.x + threadIdx.x;
    if (i < kHID)              dst[i] = bq[i];
    else if (i < 2 * kHID)     dst[i] = bk[i - kHID];
    else if (i < 3 * kHID)     dst[i] = bv[i - 2 * kHID];
}

// ===========================================================================
// fp16 GEMM, templated on number of B terms:
//  BTERMS=1: aH bH              (A hi, B hi)         -- QKV projection
//  BTERMS=2: aH bH + aH bL      (A hi, B hi+lo)      -- O projection
// Output: packed fp16 (Ch != null, with col scale) or fp32 + bias (Cf).
// cp.async 2-stage, 2 CTAs/SM, ldmatrix fragments.
// ===========================================================================
constexpr int GW    = 16;
constexpr int GSTR  = 20;
constexpr int GT    = 128 * GSTR;
constexpr int GEMM_SMEM1 = 2 * 2 * GT * 4;   // 40960 B
constexpr int GEMM_SMEM2 = 2 * 3 * GT * 4;   // 61440 B

template <int BTERMS>
__global__ __launch_bounds__(256, 2)
void gemm_f16(const uint32_t* __restrict__ Ah,
              const uint32_t* __restrict__ Bh, const uint32_t* __restrict__ Bl,
              const float* __restrict__ bias,
              float* __restrict__ Cf,
              uint32_t* __restrict__ Ch,
              int M, int N, int K, int scaleCols, float scaleVal)
{
    extern __shared__ uint32_t smw[];
    constexpr int NARR = 1 + BTERMS;
    constexpr int GSTAGE = NARR * GT;
    const uint32_t sb = smem_u32(smw);

    const int tid  = threadIdx.x;
    const int wid  = tid >> 5;
    const int lane = tid & 31;
    const int g    = lane >> 2;
    const int t    = lane & 3;

    const int wm = (wid & 3) * 32;
    const int wn = (wid >> 2) * 64;

    const int lm8 = lane & 7;
    const int lq  = lane >> 3;
    const int a_row = lm8 + (lq & 1) * 8;
    const int a_wof = (lq >> 1) * 4;
    const int b_row = lm8 + (lq >> 1) * 8;
    const int b_wof = (lq & 1) * 4;

    const int brow = blockIdx.y * 128;
    const int bcol = blockIdx.x * 128;
    const int kw   = K >> 1;
    const int nchunks = K / 32;

    const int lr0 = tid >> 2;
    const int lw4 = (tid & 3) * 4;

    float acc[2][8][4];
    #pragma unroll
    for (int mi = 0; mi < 2; mi++)
        #pragma unroll
        for (int nf = 0; nf < 8; nf++)
            #pragma unroll
            for (int j = 0; j < 4; j++) acc[mi][nf][j] = 0.f;

    auto cpa_chunk = [&](int c, int buf) {
        const uint32_t s = sb + (uint32_t)((buf * GSTAGE) << 2);
        const uint32_t* a_h = Ah + (size_t)brow * kw + c * GW + lw4;
        const uint32_t* b_h = Bh + (size_t)bcol * kw + c * GW + lw4;
        #pragma unroll
        for (int j = 0; j < 2; j++) {
            const int r = lr0 + 64 * j;
            const uint32_t d = (uint32_t)((r * GSTR + lw4) << 2);
            cp_async16(s + ((0 * GT) << 2) + d, a_h + (size_t)r * kw);
            cp_async16(s + ((1 * GT) << 2) + d, b_h + (size_t)r * kw);
            if (BTERMS == 2) {
                const uint32_t* b_l = Bl + (size_t)bcol * kw + c * GW + lw4;
                cp_async16(s + ((2 * GT) << 2) + d, b_l + (size_t)r * kw);
            }
        }
        cp_commit();
    };

    cpa_chunk(0, 0);

    for (int c = 0; c < nchunks; c++) {
        cp_wait0();
        __syncthreads();
        if (c + 1 < nchunks) cpa_chunk(c + 1, (c + 1) & 1);

        const uint32_t base = sb + (uint32_t)(((c & 1) * GSTAGE) << 2);

        #pragma unroll
        for (int kk = 0; kk < 2; kk++) {
            const int k0 = kk * 8;
            uint32_t aH[2][4];
            #pragma unroll
            for (int mi = 0; mi < 2; mi++) {
                uint32_t arow = (uint32_t)((wm + mi * 16 + a_row) * GSTR + k0 + a_wof);
                ldsm_x4(aH[mi][0], aH[mi][1], aH[mi][2], aH[mi][3],
                        base + ((0 * GT + arow) << 2));
            }
            #pragma unroll
            for (int np = 0; np < 4; np++) {
                uint32_t nrow = (uint32_t)((wn + np * 16 + b_row) * GSTR + k0 + b_wof);
                uint32_t bh[4], bl[4];
                ldsm_x4(bh[0], bh[1], bh[2], bh[3],
                        base + ((1 * GT + nrow) << 2));
                if (BTERMS == 2)
                    ldsm_x4(bl[0], bl[1], bl[2], bl[3],
                            base + ((2 * GT + nrow) << 2));
                #pragma unroll
                for (int mi = 0; mi < 2; mi++)
                    #pragma unroll
                    for (int half = 0; half < 2; half++)
                        mma_f16(acc[mi][np * 2 + half], aH[mi], bh + 2 * half);
                if (BTERMS == 2) {
                    #pragma unroll
                    for (int mi = 0; mi < 2; mi++)
                        #pragma unroll
                        for (int half = 0; half < 2; half++)
                            mma_f16(acc[mi][np * 2 + half], aH[mi], bl + 2 * half);
                }
            }
        }
    }

    const int nw = N >> 1;
    #pragma unroll
    for (int mi = 0; mi < 2; mi++) {
        const int r0 = brow + wm + mi * 16 + g;
        #pragma unroll
        for (int nf = 0; nf < 8; nf++) {
            const int c0 = bcol + wn + nf * 8 + 2 * t;
            float bx = bias[c0], by = bias[c0 + 1];
            float v0 = acc[mi][nf][0] + bx, v1 = acc[mi][nf][1] + by;
            float v2 = acc[mi][nf][2] + bx, v3 = acc[mi][nf][3] + by;
            if (Cf) {
                *(float2*)(Cf + (size_t)r0 * N + c0)       = make_float2(v0, v1);
                *(float2*)(Cf + (size_t)(r0 + 8) * N + c0) = make_float2(v2, v3);
            } else {
                float sc = (c0 < scaleCols) ? scaleVal : 1.0f;
                Ch[(size_t)r0 * nw + (c0 >> 1)]       = f16x2_pack(v0 * sc, v1 * sc);
                Ch[(size_t)(r0 + 8) * nw + (c0 >> 1)] = f16x2_pack(v2 * sc, v3 * sc);
            }
        }
    }
}

// ===========================================================================
// fp16 1-term flash attention, 2 CTAs/SM, exp/PV interleave.
// QK: qH x kH ; PV: p x vH.  K/V staged hi-only; V trans-ldmatrix.
// Output ctx packed single fp16 (for fp16 2-term O projection).
// ===========================================================================
constexpr int QSTR = 36;
constexpr int AT_Q  = 128 * QSTR;
constexpr int AT_KV = 64 * QSTR;
constexpr int AT_STAGE = 2 * AT_KV;          // KH VH
constexpr int ATTN_SMEM = (AT_Q + 2 * AT_STAGE) * 4;  // 55,296 B

__global__ __launch_bounds__(256, 2)
void attn_f16(const uint32_t* __restrict__ Qh, uint32_t* __restrict__ Oh)
{
    extern __shared__ uint32_t smw[];
    const uint32_t sb = smem_u32(smw);
    const uint32_t qhb = sb;
    const uint32_t stg = qhb + (uint32_t)(AT_Q << 2);
    const uint32_t kvb = (uint32_t)(AT_KV << 2);

    const int tid  = threadIdx.x;
    const int w    = tid >> 5;
    const int lane = tid & 31;
    const int g    = lane >> 2;
    const int t    = lane & 3;

    const int lm8 = lane & 7;
    const int lq  = lane >> 3;
    const int a_row = lm8 + (lq & 1) * 8;
    const int a_wof = (lq >> 1) * 4;
    const int b_row = lm8 + (lq >> 1) * 8;
    const int b_wof = (lq & 1) * 4;
    const int v_row = lm8 + (lq & 1) * 8;
    const int v_wof = (lq >> 1) * 4;

    const int bh = blockIdx.y;
    const int b  = bh >> 4;
    const int h  = bh & 15;
    const int q0 = blockIdx.x * 128;

    const size_t rowbase = (size_t)(b * kS) * kQKVW;
    const int qoff = h * 32;
    const int koff = 512 + h * 32;
    const int voff = 1024 + h * 32;

    // ---- stage Q (hi only) ----
    {
        #pragma unroll
        for (int i = 0; i < 4; i++) {
            int idx = tid + 256 * i;
            int r   = idx >> 3;
            int ch  = (idx & 7) * 4;
            const uint32_t* src = Qh + rowbase
                                + (size_t)(q0 + r) * kQKVW + qoff + ch;
            cp_async16(qhb + (uint32_t)((r * QSTR + ch) << 2), src);
        }
        cp_commit();
    }

    float o[8][4];
    #pragma unroll
    for (int nf = 0; nf < 8; nf++)
        #pragma unroll
        for (int e = 0; e < 4; e++) o[nf][e] = 0.f;
    float lsum0 = 0.f, lsum1 = 0.f;

    auto cpa_tile = [&](int kt, int buf) {
        const uint32_t s = stg + (uint32_t)((buf * AT_STAGE) << 2);
        #pragma unroll
        for (int i = 0; i < 4; i++) {
            int idx = tid + 256 * i;            // 0..1023
            int arr = idx >> 9;                 // 0:KH 1:VH
            int rem = idx & 511;
            int key = rem >> 3;
            int ch  = (rem & 7) * 4;
            int off = arr ? voff : koff;
            const uint32_t* src = Qh + rowbase
                                + (size_t)(kt + key) * kQKVW + off + ch;
            uint32_t dst = s + (uint32_t)((arr * AT_KV + key * QSTR + ch) << 2);
            cp_async16(dst, src);
        }
        cp_commit();
    };

    cpa_tile(0, 0);

    for (int tI = 0; tI < kS / 64; tI++) {
        cp_wait0();
        __syncthreads();
        if (tI + 1 < kS / 64) cpa_tile((tI + 1) * 64, (tI + 1) & 1);

        const uint32_t stb = stg + (uint32_t)(((tI & 1) * AT_STAGE) << 2);

        // ---- S = qH kH ----
        float s[8][4];
        #pragma unroll
        for (int nf = 0; nf < 8; nf++)
            s[nf][0] = s[nf][1] = s[nf][2] = s[nf][3] = 0.f;

        #pragma unroll
        for (int ks = 0; ks < 4; ks++) {
            const int k0 = ks * 8;
            uint32_t qH[4];
            uint32_t qrow = (uint32_t)(((w * 16 + a_row) * QSTR + k0 + a_wof) << 2);
            ldsm_x4(qH[0], qH[1], qH[2], qH[3], qhb + qrow);
            #pragma unroll
            for (int npp = 0; npp < 2; npp++) {
                uint32_t kh[2][4];
                #pragma unroll
                for (int j = 0; j < 2; j++) {
                    const int np = npp * 2 + j;
                    uint32_t roff = (uint32_t)(((np * 16 + b_row) * QSTR + k0 + b_wof) << 2);
                    ldsm_x4(kh[j][0], kh[j][1], kh[j][2], kh[j][3], stb + roff);
                }
                #pragma unroll
                for (int j = 0; j < 2; j++)
                    #pragma unroll
                    for (int half = 0; half < 2; half++)
                        mma_f16(s[npp * 4 + j * 2 + half], qH, kh[j] + 2 * half);
            }
        }

        // ---- per-kc: exp + pack + PV ----
        #pragma unroll
        for (int kc = 0; kc < 4; kc++) {
            float p00 = __expf(s[2*kc][0]);
            float p01 = __expf(s[2*kc][1]);
            float p02 = __expf(s[2*kc][2]);
            float p03 = __expf(s[2*kc][3]);
            float p10 = __expf(s[2*kc+1][0]);
            float p11 = __expf(s[2*kc+1][1]);
            float p12 = __expf(s[2*kc+1][2]);
            float p13 = __expf(s[2*kc+1][3]);
            lsum0 += p00 + p01 + p10 + p11;
            lsum1 += p02 + p03 + p12 + p13;

            uint32_t pa[4];
            pa[0] = f16x2_pack(p00, p01);
            pa[1] = f16x2_pack(p02, p03);
            pa[2] = f16x2_pack(p10, p11);
            pa[3] = f16x2_pack(p12, p13);

            #pragma unroll
            for (int npp = 0; npp < 2; npp++) {
                uint32_t vh[2][4];
                #pragma unroll
                for (int j = 0; j < 2; j++) {
                    const int np = npp * 2 + j;
                    uint32_t roff = (uint32_t)(
                        ((kc * 16 + v_row) * QSTR + np * 8 + v_wof) << 2);
                    ldsm_x4_t(vh[j][0], vh[j][1], vh[j][2], vh[j][3],
                              stb + kvb + roff);
                }
                #pragma unroll
                for (int j = 0; j < 2; j++)
                    #pragma unroll
                    for (int half = 0; half < 2; half++)
                        mma_f16(o[npp * 4 + j * 2 + half], pa, vh[j] + 2 * half);
            }
        }
    }

    // ---- reduce, normalize, pack fp16, store ctx ----
    lsum0 += __shfl_xor_sync(0xFFFFFFFFu, lsum0, 1);
    lsum0 += __shfl_xor_sync(0xFFFFFFFFu, lsum0, 2);
    lsum1 += __shfl_xor_sync(0xFFFFFFFFu, lsum1, 1);
    lsum1 += __shfl_xor_sync(0xFFFFFFFFu, lsum1, 2);
    const float inv0 = 1.f / lsum0;
    const float inv1 = 1.f / lsum1;

    const size_t row0 = (size_t)(b * kS + q0 + w * 16 + g);
    #pragma unroll
    for (int nf = 0; nf < 8; nf++) {
        const int cw = h * 32 + nf * 4 + t;
        Oh[row0 * kRW + cw]       = f16x2_pack(o[nf][0] * inv0, o[nf][1] * inv0);
        Oh[(row0 + 8) * kRW + cw] = f16x2_pack(o[nf][2] * inv1, o[nf][3] * inv1);
    }
}

// ===========================================================================
// launch
// ===========================================================================
extern "C" void kernel_launch(void* const* d_in, const int* in_sizes, int n_in,
                              void* d_out, int out_size)
{
    const float* x  = (const float*)d_in[0];
    const float* Wq = (const float*)d_in[1];
    const float* bq = (const float*)d_in[2];
    const float* Wk = (const float*)d_in[3];
    const float* bk = (const float*)d_in[4];
    const float* Wv = (const float*)d_in[5];
    const float* bv = (const float*)d_in[6];
    const float* Wo = (const float*)d_in[7];
    const float* bo = (const float*)d_in[8];
    float* out = (float*)d_out;

    uint32_t *xs_hi, *wall_hi, *wo_hi, *wo_lo, *qkv_hi, *ctx_hi;
    float* bias_all;
    cudaGetSymbolAddress((void**)&xs_hi,   g_xs_hi);
    cudaGetSymbolAddress((void**)&wall_hi, g_wall_hi);
    cudaGetSymbolAddress((void**)&wo_hi,   g_wo_hi);
    cudaGetSymbolAddress((void**)&wo_lo,   g_wo_lo);
    cudaGetSymbolAddress((void**)&bias_all,g_bias_all);
    cudaGetSymbolAddress((void**)&qkv_hi,  g_qkv_hi);
    cudaGetSymbolAddress((void**)&ctx_hi,  g_ctx_hi);

    cudaFuncSetAttribute(gemm_f16<1>,
                         cudaFuncAttributeMaxDynamicSharedMemorySize, GEMM_SMEM1);
    cudaFuncSetAttribute(gemm_f16<2>,
                         cudaFuncAttributeMaxDynamicSharedMemorySize, GEMM_SMEM2);
    cudaFuncSetAttribute(attn_f16,
                         cudaFuncAttributeMaxDynamicSharedMemorySize, ATTN_SMEM);

    const int wq4 = kHID * kD / 4;   // 262144
    split_x_f16hi<<<kM * kD / 4 / 256, 256>>>(x, xs_hi, kM * kD / 4);
    split_w4_kernel<<<4 * wq4 / 256, 256>>>(Wq, Wk, Wv, Wo,
                                            wall_hi, wo_hi, wo_lo, wq4);
    bias3_kernel<<<12, 256>>>(bq, bk, bv, bias_all);

    // fused QKV projection (fp16 1-term): output packed fp16; Q scaled 1/32
    dim3 gqkv(3 * kHID / 128, kM / 128);   // (24, 32)
    gemm_f16<1><<<gqkv, 256, GEMM_SMEM1>>>(
        xs_hi, wall_hi, nullptr, bias_all,
        nullptr, qkv_hi, kM, 3 * kHID, kD, kHID, kScale);

    dim3 ga(kS / 128, kB * kH);            // (16, 32)
    attn_f16<<<ga, 256, ATTN_SMEM>>>(qkv_hi, ctx_hi);

    // output projection (fp16 2-term: ctxH x (woH + woL)), fp32 out
    dim3 go(kD / 128, kM / 128);           // (8, 32)
    gemm_f16<2><<<go, 256, GEMM_SMEM2>>>(
        ctx_hi, wo_hi, wo_lo, bo,
        out, nullptr, kM, kD, kHID, 0, 1.0f);
}

// round 17
// speedup vs baseline: 2.2839x; 1.0703x over previous
#include <cuda_runtime.h>
#include <cuda_bf16.h>
#include <cuda_fp16.h>
#include <cstdint>
#include <cstddef>

// ===========================================================================
// Problem constants
// ===========================================================================
constexpr int kB   = 2;
constexpr int kS   = 2048;
constexpr int kD   = 1024;
constexpr int kHID = 1024;
constexpr int kH   = 16;
constexpr int kHD  = 64;
constexpr int kM   = kB * kS;      // 4096
constexpr float kScale = 0.03125f; // 1/sqrt(1024), exact power of two

constexpr int kRW   = kD / 2;      // 512 words per row (K=1024 packed)
constexpr int kQKVW = 3 * kRW;     // 1536 words per qkv row

// ===========================================================================
// Scratch (device globals; allocation-free rule)
// ===========================================================================
__device__ uint32_t g_xs_hi [(size_t)kM * kRW];           // fp16 pairs
__device__ uint32_t g_wall_hi[(size_t)3 * kHID * kRW];    // fp16 pairs
__device__ uint32_t g_wo_hi [(size_t)kD * kRW];           // fp16 pairs
__device__ uint32_t g_wo_lo [(size_t)kD * kRW];           // fp16 pairs
__device__ float    g_bias_all[3 * kHID];
__device__ uint32_t g_qkv_hi[(size_t)kM * kQKVW];         // fp16 pairs
__device__ uint32_t g_ctx_hi[(size_t)kM * kRW];           // fp16 pairs

// ===========================================================================
// helpers
// ===========================================================================
__device__ __forceinline__ void mma_f16(float* d, const uint32_t* a, const uint32_t* b) {
    asm volatile(
        "mma.sync.aligned.m16n8k16.row.col.f32.f16.f16.f32 "
        "{%0,%1,%2,%3}, {%4,%5,%6,%7}, {%8,%9}, {%0,%1,%2,%3};"
        : "+f"(d[0]), "+f"(d[1]), "+f"(d[2]), "+f"(d[3])
        : "r"(a[0]), "r"(a[1]), "r"(a[2]), "r"(a[3]),
          "r"(b[0]), "r"(b[1]));
}

__device__ __forceinline__ void ldsm_x4(uint32_t& r0, uint32_t& r1,
                                        uint32_t& r2, uint32_t& r3, uint32_t addr) {
    asm volatile(
        "ldmatrix.sync.aligned.m8n8.x4.shared.b16 {%0,%1,%2,%3}, [%4];"
        : "=r"(r0), "=r"(r1), "=r"(r2), "=r"(r3) : "r"(addr));
}

__device__ __forceinline__ void ldsm_x4_t(uint32_t& r0, uint32_t& r1,
                                          uint32_t& r2, uint32_t& r3, uint32_t addr) {
    asm volatile(
        "ldmatrix.sync.aligned.m8n8.x4.trans.shared.b16 {%0,%1,%2,%3}, [%4];"
        : "=r"(r0), "=r"(r1), "=r"(r2), "=r"(r3) : "r"(addr));
}

__device__ __forceinline__ uint32_t smem_u32(const void* p) {
    uint32_t a;
    asm("{ .reg .u64 t; cvta.to.shared.u64 t, %1; cvt.u32.u64 %0, t; }"
        : "=r"(a) : "l"(p));
    return a;
}

__device__ __forceinline__ void cp_async16(uint32_t smem_addr, const void* gmem) {
    asm volatile("cp.async.cg.shared.global [%0], [%1], 16;"
                 :: "r"(smem_addr), "l"(gmem));
}
__device__ __forceinline__ void cp_commit() {
    asm volatile("cp.async.commit_group;");
}
__device__ __forceinline__ void cp_wait0() {
    asm volatile("cp.async.wait_group 0;");
}

__device__ __forceinline__ void f16x2_split(float x0, float x1,
                                            uint32_t& hi, uint32_t& lo) {
    __half h0 = __float2half_rn(x0);
    __half h1 = __float2half_rn(x1);
    float r0 = x0 - __half2float(h0);
    float r1 = x1 - __half2float(h1);
    __half l0 = __float2half_rn(r0);
    __half l1 = __float2half_rn(r1);
    hi = ((uint32_t)__half_as_ushort(h1) << 16) | __half_as_ushort(h0);
    lo = ((uint32_t)__half_as_ushort(l1) << 16) | __half_as_ushort(l0);
}

__device__ __forceinline__ uint32_t f16x2_pack(float x0, float x1) {
    uint32_t w;
    asm("cvt.rn.f16x2.f32 %0, %1, %2;" : "=r"(w) : "f"(x1), "f"(x0));
    return w;
}

// ===========================================================================
// split kernels
// ===========================================================================
__global__ void split_x_f16hi(const float* __restrict__ src,
                              uint32_t* __restrict__ hi, int n4)
{
    int i = blockIdx.x * blockDim.x + threadIdx.x;
    if (i >= n4) return;
    float4 v = ((const float4*)src)[i];
    ((uint2*)hi)[i] = make_uint2(f16x2_pack(v.x, v.y), f16x2_pack(v.z, v.w));
}

__global__ void split_w4_kernel(const float* __restrict__ Wq,
                                const float* __restrict__ Wk,
                                const float* __restrict__ Wv,
                                const float* __restrict__ Wo,
                                uint32_t* __restrict__ wall_hi,
                                uint32_t* __restrict__ wo_hi,
                                uint32_t* __restrict__ wo_lo,
                                int n4region)
{
    int gi = blockIdx.x * blockDim.x + threadIdx.x;
    int region = gi / n4region;
    int i = gi - region * n4region;
    const float* src = (region == 0) ? Wq : (region == 1) ? Wk
                     : (region == 2) ? Wv : Wo;
    float4 v = ((const float4*)src)[i];
    if (region < 3) {
        uint32_t* hi = wall_hi + (size_t)region * 2 * n4region;
        ((uint2*)hi)[i] = make_uint2(f16x2_pack(v.x, v.y), f16x2_pack(v.z, v.w));
    } else {
        uint32_t h0, l0, h1, l1;
        f16x2_split(v.x, v.y, h0, l0);
        f16x2_split(v.z, v.w, h1, l1);
        ((uint2*)wo_hi)[i] = make_uint2(h0, h1);
        ((uint2*)wo_lo)[i] = make_uint2(l0, l1);
    }
}

__global__ void bias3_kernel(const float* __restrict__ bq,
                             const float* __restrict__ bk,
                             const float* __restrict__ bv,
                             float* __restrict__ dst)
{
    int i = blockIdx.x * blockDim.x + threadIdx.x;
    if (i < kHID)              dst[i] = bq[i];
    else if (i < 2 * kHID)     dst[i] = bk[i - kHID];
    else if (i < 3 * kHID)     dst[i] = bv[i - 2 * kHID];
}

// ===========================================================================
// fp16 GEMM, BK=64 (32 words/chunk), templated on B terms:
//  BTERMS=1: aH bH          -- QKV projection
//  BTERMS=2: aH (bH + bL)   -- O projection
// cp.async 2-stage, 2 CTAs/SM, ldmatrix fragments.
// ===========================================================================
constexpr int GW    = 32;              // words per row per chunk (64 elems)
constexpr int GSTR  = 36;              // padded word stride
constexpr int GT    = 128 * GSTR;      // words per tile array (4608)
constexpr int GEMM_SMEM1 = 2 * 2 * GT * 4;   // 73728 B
constexpr int GEMM_SMEM2 = 2 * 3 * GT * 4;   // 110592 B

template <int BTERMS>
__global__ __launch_bounds__(256, 2)
void gemm_f16(const uint32_t* __restrict__ Ah,
              const uint32_t* __restrict__ Bh, const uint32_t* __restrict__ Bl,
              const float* __restrict__ bias,
              float* __restrict__ Cf,
              uint32_t* __restrict__ Ch,
              int M, int N, int K, int scaleCols, float scaleVal)
{
    extern __shared__ uint32_t smw[];
    constexpr int NARR = 1 + BTERMS;
    constexpr int GSTAGE = NARR * GT;
    const uint32_t sb = smem_u32(smw);

    const int tid  = threadIdx.x;
    const int wid  = tid >> 5;
    const int lane = tid & 31;
    const int g    = lane >> 2;
    const int t    = lane & 3;

    const int wm = (wid & 3) * 32;
    const int wn = (wid >> 2) * 64;

    const int lm8 = lane & 7;
    const int lq  = lane >> 3;
    const int a_row = lm8 + (lq & 1) * 8;
    const int a_wof = (lq >> 1) * 4;
    const int b_row = lm8 + (lq >> 1) * 8;
    const int b_wof = (lq & 1) * 4;

    const int brow = blockIdx.y * 128;
    const int bcol = blockIdx.x * 128;
    const int kw   = K >> 1;
    const int nchunks = K / 64;

    // load mapping: 1024 uint4 per array; thread does 4
    const int lr0 = tid >> 3;           // row 0..31 (+32j)
    const int lw4 = (tid & 7) * 4;      // word 0..28

    float acc[2][8][4];
    #pragma unroll
    for (int mi = 0; mi < 2; mi++)
        #pragma unroll
        for (int nf = 0; nf < 8; nf++)
            #pragma unroll
            for (int j = 0; j < 4; j++) acc[mi][nf][j] = 0.f;

    auto cpa_chunk = [&](int c, int buf) {
        const uint32_t s = sb + (uint32_t)((buf * GSTAGE) << 2);
        const uint32_t* a_h = Ah + (size_t)brow * kw + c * GW + lw4;
        const uint32_t* b_h = Bh + (size_t)bcol * kw + c * GW + lw4;
        #pragma unroll
        for (int j = 0; j < 4; j++) {
            const int r = lr0 + 32 * j;
            const uint32_t d = (uint32_t)((r * GSTR + lw4) << 2);
            cp_async16(s + ((0 * GT) << 2) + d, a_h + (size_t)r * kw);
            cp_async16(s + ((1 * GT) << 2) + d, b_h + (size_t)r * kw);
            if (BTERMS == 2) {
                const uint32_t* b_l = Bl + (size_t)bcol * kw + c * GW + lw4;
                cp_async16(s + ((2 * GT) << 2) + d, b_l + (size_t)r * kw);
            }
        }
        cp_commit();
    };

    cpa_chunk(0, 0);

    for (int c = 0; c < nchunks; c++) {
        cp_wait0();
        __syncthreads();
        if (c + 1 < nchunks) cpa_chunk(c + 1, (c + 1) & 1);

        const uint32_t base = sb + (uint32_t)(((c & 1) * GSTAGE) << 2);

        #pragma unroll
        for (int kk = 0; kk < 4; kk++) {
            const int k0 = kk * 8;
            uint32_t aH[2][4];
            #pragma unroll
            for (int mi = 0; mi < 2; mi++) {
                uint32_t arow = (uint32_t)((wm + mi * 16 + a_row) * GSTR + k0 + a_wof);
                ldsm_x4(aH[mi][0], aH[mi][1], aH[mi][2], aH[mi][3],
                        base + ((0 * GT + arow) << 2));
            }
            #pragma unroll
            for (int np = 0; np < 4; np++) {
                uint32_t nrow = (uint32_t)((wn + np * 16 + b_row) * GSTR + k0 + b_wof);
                uint32_t bh[4], bl[4];
                ldsm_x4(bh[0], bh[1], bh[2], bh[3],
                        base + ((1 * GT + nrow) << 2));
                if (BTERMS == 2)
                    ldsm_x4(bl[0], bl[1], bl[2], bl[3],
                            base + ((2 * GT + nrow) << 2));
                #pragma unroll
                for (int mi = 0; mi < 2; mi++)
                    #pragma unroll
                    for (int half = 0; half < 2; half++)
                        mma_f16(acc[mi][np * 2 + half], aH[mi], bh + 2 * half);
                if (BTERMS == 2) {
                    #pragma unroll
                    for (int mi = 0; mi < 2; mi++)
                        #pragma unroll
                        for (int half = 0; half < 2; half++)
                            mma_f16(acc[mi][np * 2 + half], aH[mi], bl + 2 * half);
                }
            }
        }
    }

    const int nw = N >> 1;
    #pragma unroll
    for (int mi = 0; mi < 2; mi++) {
        const int r0 = brow + wm + mi * 16 + g;
        #pragma unroll
        for (int nf = 0; nf < 8; nf++) {
            const int c0 = bcol + wn + nf * 8 + 2 * t;
            float bx = bias[c0], by = bias[c0 + 1];
            float v0 = acc[mi][nf][0] + bx, v1 = acc[mi][nf][1] + by;
            float v2 = acc[mi][nf][2] + bx, v3 = acc[mi][nf][3] + by;
            if (Cf) {
                *(float2*)(Cf + (size_t)r0 * N + c0)       = make_float2(v0, v1);
                *(float2*)(Cf + (size_t)(r0 + 8) * N + c0) = make_float2(v2, v3);
            } else {
                float sc = (c0 < scaleCols) ? scaleVal : 1.0f;
                Ch[(size_t)r0 * nw + (c0 >> 1)]       = f16x2_pack(v0 * sc, v1 * sc);
                Ch[(size_t)(r0 + 8) * nw + (c0 >> 1)] = f16x2_pack(v2 * sc, v3 * sc);
            }
        }
    }
}

// ===========================================================================
// fp16 1-term flash attention (unchanged from R16), 2 CTAs/SM.
// ===========================================================================
constexpr int QSTR = 36;
constexpr int AT_Q  = 128 * QSTR;
constexpr int AT_KV = 64 * QSTR;
constexpr int AT_STAGE = 2 * AT_KV;          // KH VH
constexpr int ATTN_SMEM = (AT_Q + 2 * AT_STAGE) * 4;  // 55,296 B

__global__ __launch_bounds__(256, 2)
void attn_f16(const uint32_t* __restrict__ Qh, uint32_t* __restrict__ Oh)
{
    extern __shared__ uint32_t smw[];
    const uint32_t sb = smem_u32(smw);
    const uint32_t qhb = sb;
    const uint32_t stg = qhb + (uint32_t)(AT_Q << 2);
    const uint32_t kvb = (uint32_t)(AT_KV << 2);

    const int tid  = threadIdx.x;
    const int w    = tid >> 5;
    const int lane = tid & 31;
    const int g    = lane >> 2;
    const int t    = lane & 3;

    const int lm8 = lane & 7;
    const int lq  = lane >> 3;
    const int a_row = lm8 + (lq & 1) * 8;
    const int a_wof = (lq >> 1) * 4;
    const int b_row = lm8 + (lq >> 1) * 8;
    const int b_wof = (lq & 1) * 4;
    const int v_row = lm8 + (lq & 1) * 8;
    const int v_wof = (lq >> 1) * 4;

    const int bh = blockIdx.y;
    const int b  = bh >> 4;
    const int h  = bh & 15;
    const int q0 = blockIdx.x * 128;

    const size_t rowbase = (size_t)(b * kS) * kQKVW;
    const int qoff = h * 32;
    const int koff = 512 + h * 32;
    const int voff = 1024 + h * 32;

    // ---- stage Q (hi only) ----
    {
        #pragma unroll
        for (int i = 0; i < 4; i++) {
            int idx = tid + 256 * i;
            int r   = idx >> 3;
            int ch  = (idx & 7) * 4;
            const uint32_t* src = Qh + rowbase
                                + (size_t)(q0 + r) * kQKVW + qoff + ch;
            cp_async16(qhb + (uint32_t)((r * QSTR + ch) << 2), src);
        }
        cp_commit();
    }

    float o[8][4];
    #pragma unroll
    for (int nf = 0; nf < 8; nf++)
        #pragma unroll
        for (int e = 0; e < 4; e++) o[nf][e] = 0.f;
    float lsum0 = 0.f, lsum1 = 0.f;

    auto cpa_tile = [&](int kt, int buf) {
        const uint32_t s = stg + (uint32_t)((buf * AT_STAGE) << 2);
        #pragma unroll
        for (int i = 0; i < 4; i++) {
            int idx = tid + 256 * i;            // 0..1023
            int arr = idx >> 9;                 // 0:KH 1:VH
            int rem = idx & 511;
            int key = rem >> 3;
            int ch  = (rem & 7) * 4;
            int off = arr ? voff : koff;
            const uint32_t* src = Qh + rowbase
                                + (size_t)(kt + key) * kQKVW + off + ch;
            uint32_t dst = s + (uint32_t)((arr * AT_KV + key * QSTR + ch) << 2);
            cp_async16(dst, src);
        }
        cp_commit();
    };

    cpa_tile(0, 0);

    for (int tI = 0; tI < kS / 64; tI++) {
        cp_wait0();
        __syncthreads();
        if (tI + 1 < kS / 64) cpa_tile((tI + 1) * 64, (tI + 1) & 1);

        const uint32_t stb = stg + (uint32_t)(((tI & 1) * AT_STAGE) << 2);

        // ---- S = qH kH ----
        float s[8][4];
        #pragma unroll
        for (int nf = 0; nf < 8; nf++)
            s[nf][0] = s[nf][1] = s[nf][2] = s[nf][3] = 0.f;

        #pragma unroll
        for (int ks = 0; ks < 4; ks++) {
            const int k0 = ks * 8;
            uint32_t qH[4];
            uint32_t qrow = (uint32_t)(((w * 16 + a_row) * QSTR + k0 + a_wof) << 2);
            ldsm_x4(qH[0], qH[1], qH[2], qH[3], qhb + qrow);
            #pragma unroll
            for (int npp = 0; npp < 2; npp++) {
                uint32_t kh[2][4];
                #pragma unroll
                for (int j = 0; j < 2; j++) {
                    const int np = npp * 2 + j;
                    uint32_t roff = (uint32_t)(((np * 16 + b_row) * QSTR + k0 + b_wof) << 2);
                    ldsm_x4(kh[j][0], kh[j][1], kh[j][2], kh[j][3], stb + roff);
                }
                #pragma unroll
                for (int j = 0; j < 2; j++)
                    #pragma unroll
                    for (int half = 0; half < 2; half++)
                        mma_f16(s[npp * 4 + j * 2 + half], qH, kh[j] + 2 * half);
            }
        }

        // ---- per-kc: exp + pack + PV ----
        #pragma unroll
        for (int kc = 0; kc < 4; kc++) {
            float p00 = __expf(s[2*kc][0]);
            float p01 = __expf(s[2*kc][1]);
            float p02 = __expf(s[2*kc][2]);
            float p03 = __expf(s[2*kc][3]);
            float p10 = __expf(s[2*kc+1][0]);
            float p11 = __expf(s[2*kc+1][1]);
            float p12 = __expf(s[2*kc+1][2]);
            float p13 = __expf(s[2*kc+1][3]);
            lsum0 += p00 + p01 + p10 + p11;
            lsum1 += p02 + p03 + p12 + p13;

            uint32_t pa[4];
            pa[0] = f16x2_pack(p00, p01);
            pa[1] = f16x2_pack(p02, p03);
            pa[2] = f16x2_pack(p10, p11);
            pa[3] = f16x2_pack(p12, p13);

            #pragma unroll
            for (int npp = 0; npp < 2; npp++) {
                uint32_t vh[2][4];
                #pragma unroll
                for (int j = 0; j < 2; j++) {
                    const int np = npp * 2 + j;
                    uint32_t roff = (uint32_t)(
                        ((kc * 16 + v_row) * QSTR + np * 8 + v_wof) << 2);
                    ldsm_x4_t(vh[j][0], vh[j][1], vh[j][2], vh[j][3],
                              stb + kvb + roff);
                }
                #pragma unroll
                for (int j = 0; j < 2; j++)
                    #pragma unroll
                    for (int half = 0; half < 2; half++)
                        mma_f16(o[npp * 4 + j * 2 + half], pa, vh[j] + 2 * half);
            }
        }
    }

    // ---- reduce, normalize, pack fp16, store ctx ----
    lsum0 += __shfl_xor_sync(0xFFFFFFFFu, lsum0, 1);
    lsum0 += __shfl_xor_sync(0xFFFFFFFFu, lsum0, 2);
    lsum1 += __shfl_xor_sync(0xFFFFFFFFu, lsum1, 1);
    lsum1 += __shfl_xor_sync(0xFFFFFFFFu, lsum1, 2);
    const float inv0 = 1.f / lsum0;
    const float inv1 = 1.f / lsum1;

    const size_t row0 = (size_t)(b * kS + q0 + w * 16 + g);
    #pragma unroll
    for (int nf = 0; nf < 8; nf++) {
        const int cw = h * 32 + nf * 4 + t;
        Oh[row0 * kRW + cw]       = f16x2_pack(o[nf][0] * inv0, o[nf][1] * inv0);
        Oh[(row0 + 8) * kRW + cw] = f16x2_pack(o[nf][2] * inv1, o[nf][3] * inv1);
    }
}

// ===========================================================================
// launch
// ===========================================================================
extern "C" void kernel_launch(void* const* d_in, const int* in_sizes, int n_in,
                              void* d_out, int out_size)
{
    const float* x  = (const float*)d_in[0];
    const float* Wq = (const float*)d_in[1];
    const float* bq = (const float*)d_in[2];
    const float* Wk = (const float*)d_in[3];
    const float* bk = (const float*)d_in[4];
    const float* Wv = (const float*)d_in[5];
    const float* bv = (const float*)d_in[6];
    const float* Wo = (const float*)d_in[7];
    const float* bo = (const float*)d_in[8];
    float* out = (float*)d_out;

    uint32_t *xs_hi, *wall_hi, *wo_hi, *wo_lo, *qkv_hi, *ctx_hi;
    float* bias_all;
    cudaGetSymbolAddress((void**)&xs_hi,   g_xs_hi);
    cudaGetSymbolAddress((void**)&wall_hi, g_wall_hi);
    cudaGetSymbolAddress((void**)&wo_hi,   g_wo_hi);
    cudaGetSymbolAddress((void**)&wo_lo,   g_wo_lo);
    cudaGetSymbolAddress((void**)&bias_all,g_bias_all);
    cudaGetSymbolAddress((void**)&qkv_hi,  g_qkv_hi);
    cudaGetSymbolAddress((void**)&ctx_hi,  g_ctx_hi);

    cudaFuncSetAttribute(gemm_f16<1>,
                         cudaFuncAttributeMaxDynamicSharedMemorySize, GEMM_SMEM1);
    cudaFuncSetAttribute(gemm_f16<2>,
                         cudaFuncAttributeMaxDynamicSharedMemorySize, GEMM_SMEM2);
    cudaFuncSetAttribute(attn_f16,
                         cudaFuncAttributeMaxDynamicSharedMemorySize, ATTN_SMEM);

    const int wq4 = kHID * kD / 4;   // 262144
    split_x_f16hi<<<kM * kD / 4 / 256, 256>>>(x, xs_hi, kM * kD / 4);
    split_w4_kernel<<<4 * wq4 / 256, 256>>>(Wq, Wk, Wv, Wo,
                                            wall_hi, wo_hi, wo_lo, wq4);
    bias3_kernel<<<12, 256>>>(bq, bk, bv, bias_all);

    // fused QKV projection (fp16 1-term, BK=64): output packed fp16; Q scaled 1/32
    dim3 gqkv(3 * kHID / 128, kM / 128);   // (24, 32)
    gemm_f16<1><<<gqkv, 256, GEMM_SMEM1>>>(
        xs_hi, wall_hi, nullptr, bias_all,
        nullptr, qkv_hi, kM, 3 * kHID, kD, kHID, kScale);

    dim3 ga(kS / 128, kB * kH);            // (16, 32)
    attn_f16<<<ga, 256, ATTN_SMEM>>>(qkv_hi, ctx_hi);

    // output projection (fp16 2-term, BK=64), fp32 out
    dim3 go(kD / 128, kM / 128);           // (8, 32)
    gemm_f16<2><<<go, 256, GEMM_SMEM2>>>(
        ctx_hi, wo_hi, wo_lo, bo,
        out, nullptr, kM, kD, kHID, 0, 1.0f);
}